// round 11
// baseline (speedup 1.0000x reference)
#include <cuda_runtime.h>
#include <cuda_fp16.h>
#include <stdint.h>

#define B_    4096
#define T_    256
#define D_    64
#define H_    256
#define NBLK  128
#define MTILE 32
#define NTHR  512          // 16 compute warps; every warp also fetches its own weights

#define NSLOT 3            // per-warp smem ring slots
#define WSLICE 3072        // bytes per warp per k32 chunk (2 k16 x 6 frags x 32 lanes x 8B)
#define QSTEP 26           // k32 chunks per timestep: L1(2+8) + L2(8+8)

// Gate weights, chunk-major: [q 0..25][w 0..15][k16 0..1][t 0..5][lane] uint2
__device__ __align__(16) uint2 g_bW[QSTEP * 16 * 2 * 6 * 32];
// Head weights (tiny, direct-LDG path)
__device__ __align__(16) uint4 g_bF[8 * 8 * 32 + 512];

// SMEM layout (bytes)
#define OFF_RING  0                 // 16 warps x 3 slots x 3072 = 147456
#define OFF_H16A  147456            // fp16 h1: 16384 (single buffer, in-place)
#define OFF_H16B  163840            // fp16 h2: 16384
#define OFF_X16   180224            // fp16 x : 4096
#define OFF_SB1   184320            // 4*256 f32
#define OFF_SB2   188416
#define OFF_SBF   192512            // 64 f32
#define SMEM_TOT  192768

__device__ __forceinline__ uint32_t pkh(float a, float b) {
    __half2 h = __floats2half2_rn(a, b);
    return *reinterpret_cast<uint32_t*>(&h);
}
__device__ __forceinline__ void mma16(float* d, const uint32_t* a,
                                      uint32_t b0, uint32_t b1) {
    asm volatile(
        "mma.sync.aligned.m16n8k16.row.col.f32.f16.f16.f32 "
        "{%0,%1,%2,%3}, {%4,%5,%6,%7}, {%8,%9}, {%0,%1,%2,%3};\n"
        : "+f"(d[0]), "+f"(d[1]), "+f"(d[2]), "+f"(d[3])
        : "r"(a[0]), "r"(a[1]), "r"(a[2]), "r"(a[3]), "r"(b0), "r"(b1));
}
__device__ __forceinline__ void ldsm4(uint32_t* r, uint32_t addr) {
    asm volatile("ldmatrix.sync.aligned.m8n8.x4.shared.b16 {%0,%1,%2,%3}, [%4];"
                 : "=r"(r[0]), "=r"(r[1]), "=r"(r[2]), "=r"(r[3]) : "r"(addr));
}
__device__ __forceinline__ float ftanh(float x) {
    float y; asm("tanh.approx.f32 %0, %1;" : "=f"(y) : "f"(x)); return y;
}
__device__ __forceinline__ float fsig(float x) {
    return fmaf(0.5f, ftanh(0.5f * x), 0.5f);
}
__device__ __forceinline__ uint32_t cvta_s(const void* p) {
    return (uint32_t)__cvta_generic_to_shared(p);
}

// ---------------------------------------------------------------------------
// Repack gate weights, chunk-major for per-warp cp.async slices.
// k16 index kk = q*2 + hh:  kk<4: Wih1(K=64,k0=16kk); kk<20: Whh1;
//                           kk<36: Wih2; else Whh2.
__global__ void repack_w(const float* __restrict__ Wih1,
                         const float* __restrict__ Whh1,
                         const float* __restrict__ Wih2,
                         const float* __restrict__ Whh2) {
    int total = QSTEP * 16 * 2 * 6 * 32;
    for (int o = blockIdx.x * blockDim.x + threadIdx.x; o < total;
         o += gridDim.x * blockDim.x) {
        int lane = o & 31, r = o >> 5;
        int t = r % 6; r /= 6;
        int hh = r & 1; r >>= 1;
        int w = r & 15; r >>= 4;
        int q = r;                       // 0..25
        int kk = q * 2 + hh;             // global k16 index
        int G = t >> 1, jt = t & 1, g = lane >> 2, tig = lane & 3;
        int n = G * H_ + w * 16 + jt * 8 + g;
        const float* W; int K, k0;
        if (kk < 4)       { W = Wih1; K = 64;  k0 = kk * 16; }
        else if (kk < 20) { W = Whh1; K = 256; k0 = (kk - 4) * 16; }
        else if (kk < 36) { W = Wih2; K = 256; k0 = (kk - 20) * 16; }
        else              { W = Whh2; K = 256; k0 = (kk - 36) * 16; }
        const float* src = W + (size_t)n * K + k0 + 2 * tig;
        uint2 v;
        v.x = pkh(src[0], src[1]);
        v.y = pkh(src[8], src[9]);
        g_bW[o] = v;
    }
}
__global__ void repack_head(const float* __restrict__ W) {
    int total = 8 * 8 * 32;
    for (int o = blockIdx.x * blockDim.x + threadIdx.x; o < total;
         o += gridDim.x * blockDim.x) {
        int lane = o & 31, s = o >> 5;
        int c2 = s & 7, w = s >> 3;
        int g = lane >> 2, tig = lane & 3;
        int n = w * 8 + g;
        const float* src = W + (size_t)n * 256 + c2 * 32 + 2 * tig;
        uint4 v;
        v.x = pkh(src[0],  src[1]);
        v.y = pkh(src[8],  src[9]);
        v.z = pkh(src[16], src[17]);
        v.w = pkh(src[24], src[25]);
        g_bF[o] = v;
    }
}

// ---------------------------------------------------------------------------
// Warp-local weight fetch: copy this warp's 3KB slice of chunk qq into slot.
__device__ __forceinline__ void fetch_chunk(uint32_t dst, const char* src) {
#pragma unroll
    for (int i = 0; i < 6; i++)
        asm volatile("cp.async.cg.shared.global [%0], [%1], 16;"
                     :: "r"(dst + (uint32_t)(i * 16)), "l"(src + i * 16));
    asm volatile("cp.async.commit_group;" ::: "memory");
}

// Consume one k32 chunk from my ring slot: 4 ldmatrix (A), 12 LDS.64 (B),
// 24 MMAs. slotB has lane*8 folded in.
__device__ __forceinline__ void consume_chunk(
    uint32_t slotB, uint32_t aBase, uint32_t kk0, uint32_t mst,
    int lhi, int sxr,
    float (&aR)[2][2][4], float (&aZ)[2][2][4], float (&aN)[2][2][4]) {
#pragma unroll
    for (int hh = 0; hh < 2; hh++) {
        uint32_t cc = (kk0 + (uint32_t)hh) * 2 + (uint32_t)lhi;
        uint32_t a0 = aBase + ((cc ^ (uint32_t)sxr) << 4);
        uint32_t af0[4], af1[4];
        ldsm4(af0, a0);
        ldsm4(af1, a0 + mst);
        uint32_t wb = slotB + (uint32_t)(hh * 1536);
#pragma unroll
        for (int t = 0; t < 6; t++) {
            uint32_t w0, w1;
            asm volatile("ld.shared.v2.u32 {%0,%1}, [%2];"
                         : "=r"(w0), "=r"(w1) : "r"(wb + (uint32_t)(t * 256)));
            float (*acc)[2][4] = (t < 2) ? aR : (t < 4) ? aZ : aN;
            int jt = t & 1;
            mma16(acc[jt][0], af0, w0, w1);
            mma16(acc[jt][1], af1, w0, w1);
        }
    }
}

// Head GEMM (warps 0-7): direct LDG of g_bF, K=256.
__device__ __forceinline__ void gemmH(uint32_t ah,
                                      const uint4* __restrict__ blobWL,
                                      int lhi, int sxr, float (&acc)[2][4]) {
    uint4 buf[8];
#pragma unroll
    for (int i = 0; i < 8; i++) buf[i] = blobWL[i * 32];
#pragma unroll 1
    for (int c2 = 0; c2 < 8; c2++) {
        uint32_t af[2][2][4];
#pragma unroll
        for (int m = 0; m < 2; m++)
#pragma unroll
            for (int ch = 0; ch < 2; ch++) {
                int cc = c2 * 4 + ch * 2 + lhi;
                uint32_t addr = (m ? ah + 16 * 512 : ah) +
                                (uint32_t)((cc ^ sxr) << 4);
                ldsm4(af[m][ch], addr);
            }
        uint4 wv = buf[c2];
        mma16(acc[0], af[0][0], wv.x, wv.y);
        mma16(acc[1], af[1][0], wv.x, wv.y);
        mma16(acc[0], af[0][1], wv.z, wv.w);
        mma16(acc[1], af[1][1], wv.z, wv.w);
    }
}

__device__ __forceinline__ void zero4(float (&aR)[2][2][4], float (&aZ)[2][2][4],
                                      float (&aNi)[2][2][4],
                                      float (&aNh)[2][2][4]) {
#pragma unroll
    for (int jt = 0; jt < 2; jt++)
#pragma unroll
        for (int m = 0; m < 2; m++)
#pragma unroll
            for (int q = 0; q < 4; q++) {
                aR[jt][m][q] = 0.f; aZ[jt][m][q] = 0.f;
                aNi[jt][m][q] = 0.f; aNh[jt][m][q] = 0.f;
            }
}

// GRU gate math; fp32 h lives in REGISTERS (hr, thread-private, fixed cells),
// fp16 h' written in place to h16 (callers barrier around it).
__device__ __forceinline__ void epilogue(float (&aR)[2][2][4], float (&aZ)[2][2][4],
                                         float (&aNi)[2][2][4],
                                         float (&aNh)[2][2][4],
                                         float (&hr)[2][2][2][2], char* h16,
                                         const float* __restrict__ sB,
                                         int w, int g, int tig) {
#pragma unroll
    for (int jt = 0; jt < 2; jt++) {
        int j0 = w * 16 + jt * 8 + 2 * tig;
        float br0 = sB[j0],          br1 = sB[j0 + 1];
        float bz0 = sB[H_ + j0],     bz1 = sB[H_ + j0 + 1];
        float bi0 = sB[2 * H_ + j0], bi1 = sB[2 * H_ + j0 + 1];
        float bh0 = sB[3 * H_ + j0], bh1 = sB[3 * H_ + j0 + 1];
        int cc = 2 * w + jt;
#pragma unroll
        for (int m = 0; m < 2; m++)
#pragma unroll
            for (int hq = 0; hq < 2; hq++) {
                int row = g + hq * 8 + m * 16;
                int q0 = hq * 2, q1 = hq * 2 + 1;
                float hc0 = hr[jt][m][hq][0], hc1 = hr[jt][m][hq][1];
                float r0 = fsig(aR[jt][m][q0] + br0);
                float r1 = fsig(aR[jt][m][q1] + br1);
                float z0 = fsig(aZ[jt][m][q0] + bz0);
                float z1 = fsig(aZ[jt][m][q1] + bz1);
                float n0 = ftanh(aNi[jt][m][q0] + bi0 + r0 * (aNh[jt][m][q0] + bh0));
                float n1 = ftanh(aNi[jt][m][q1] + bi1 + r1 * (aNh[jt][m][q1] + bh1));
                float h0 = (1.f - z0) * n0 + z0 * hc0;
                float h1 = (1.f - z1) * n1 + z1 * hc1;
                hr[jt][m][hq][0] = h0;
                hr[jt][m][hq][1] = h1;
                *reinterpret_cast<__half2*>(
                    h16 + row * 512 + ((cc ^ (row & 7)) << 4) + tig * 4) =
                    __floats2half2_rn(h0, h1);
            }
    }
}

// ---------------------------------------------------------------------------
extern __shared__ __align__(1024) char smem[];

__global__ void __launch_bounds__(NTHR, 1)
gru_main(const float* __restrict__ x, const float* __restrict__ h1g,
         const float* __restrict__ h2g,
         const float* __restrict__ bih1, const float* __restrict__ bhh1,
         const float* __restrict__ bih2, const float* __restrict__ bhh2,
         const float* __restrict__ bfc, float* __restrict__ out) {
    char*  h16_1 = smem + OFF_H16A;
    char*  h16_2 = smem + OFF_H16B;
    char*  x16   = smem + OFF_X16;
    float* sB1   = (float*)(smem + OFF_SB1);
    float* sB2   = (float*)(smem + OFF_SB2);
    float* sBf   = (float*)(smem + OFF_SBF);

    const int tid = threadIdx.x;
    const int w = tid >> 5, lane = tid & 31, g = lane >> 2, tig = lane & 3;
    const int l16 = lane & 15, lhi = lane >> 4, sxr = l16 & 7;
    const int b0 = blockIdx.x * MTILE;

    // combined biases into shared
    if (tid < 256) {
        sB1[tid]          = bih1[tid] + bhh1[tid];
        sB1[H_ + tid]     = bih1[H_ + tid] + bhh1[H_ + tid];
        sB1[2 * H_ + tid] = bih1[2 * H_ + tid];
        sB1[3 * H_ + tid] = bhh1[2 * H_ + tid];
        sB2[tid]          = bih2[tid] + bhh2[tid];
        sB2[H_ + tid]     = bih2[H_ + tid] + bhh2[H_ + tid];
        sB2[2 * H_ + tid] = bih2[2 * H_ + tid];
        sB2[3 * H_ + tid] = bhh2[2 * H_ + tid];
        if (tid < D_) sBf[tid] = bfc[tid];

        // initial fp16 h (swizzled)
        int cc = tid >> 3, cb = tid & 7;
        for (int i = 0; i < MTILE; i++) {
            float v1 = h1g[(size_t)(b0 + i) * H_ + tid];
            float v2 = h2g[(size_t)(b0 + i) * H_ + tid];
            int off = i * 512 + ((cc ^ (i & 7)) << 4) + cb * 2;
            *reinterpret_cast<__half*>(h16_1 + off) = __float2half_rn(v1);
            *reinterpret_cast<__half*>(h16_2 + off) = __float2half_rn(v2);
        }
    }

    // fp32 h in registers: hr[jt][m][hq][c] at row = g+hq*8+m*16,
    // col = w*16+jt*8+2*tig+c  (thread-private, fixed across steps)
    float h1r[2][2][2][2], h2r[2][2][2][2];
#pragma unroll
    for (int jt = 0; jt < 2; jt++)
#pragma unroll
        for (int m = 0; m < 2; m++)
#pragma unroll
            for (int hq = 0; hq < 2; hq++) {
                int row = g + hq * 8 + m * 16;
                int j0 = w * 16 + jt * 8 + 2 * tig;
                float2 v1 = *reinterpret_cast<const float2*>(
                    h1g + (size_t)(b0 + row) * H_ + j0);
                float2 v2 = *reinterpret_cast<const float2*>(
                    h2g + (size_t)(b0 + row) * H_ + j0);
                h1r[jt][m][hq][0] = v1.x; h1r[jt][m][hq][1] = v1.y;
                h2r[jt][m][hq][0] = v2.x; h2r[jt][m][hq][1] = v2.y;
            }

    // x staging (threads 0..255)
    const int xr = (tid & 255) >> 3, xcc = tid & 7;
    const float* xbase = x + ((size_t)(b0 + xr) * T_) * D_ + xcc * 8;
    const int xoff = xr * 128 + ((xcc ^ (xr & 7)) << 4);
    if (tid < 256) {
        float4 v0 = *reinterpret_cast<const float4*>(xbase);
        float4 v1 = *reinterpret_cast<const float4*>(xbase + 4);
        uint4 p;
        p.x = pkh(v0.x, v0.y); p.y = pkh(v0.z, v0.w);
        p.z = pkh(v1.x, v1.y); p.w = pkh(v1.z, v1.w);
        *reinterpret_cast<uint4*>(x16 + xoff) = p;
    }

    // shared addresses
    const uint32_t ringS = cvta_s(smem + OFF_RING);
    const uint32_t a_h1 = cvta_s(h16_1) + l16 * 512;
    const uint32_t a_h2 = cvta_s(h16_2) + l16 * 512;
    const uint32_t a_x  = cvta_s(x16) + l16 * 128;
    const uint4* bF = g_bF + (size_t)(w & 7) * 8 * 32 + lane;

    // per-warp weight stream state
    const char* srcb = (const char*)g_bW;
    const uint32_t src_off = (uint32_t)w * WSLICE + (uint32_t)lane * 96;
    const uint32_t dstB = ringS + (uint32_t)w * (NSLOT * WSLICE) +
                          (uint32_t)lane * 96;
    const uint32_t slotB = ringS + (uint32_t)w * (NSLOT * WSLICE) +
                           (uint32_t)lane * 8;

    int qqf = 0, sf = 0, sc = 0;
    // warm the per-warp ring with 2 chunks in flight
    fetch_chunk(dstB, srcb + src_off);                       // chunk 0 -> slot 0
    fetch_chunk(dstB + WSLICE, srcb + 49152 + src_off);      // chunk 1 -> slot 1
    qqf = 2; sf = 2;

    __syncthreads();

    float aR[2][2][4], aZ[2][2][4], aNi[2][2][4], aNh[2][2][4];

#define CONSUME(aBase, kk0, mst, accN)                                        \
    {                                                                         \
        asm volatile("cp.async.wait_group 1;" ::: "memory");                  \
        __syncwarp();                                                         \
        consume_chunk(slotB + (uint32_t)sc * WSLICE, aBase, kk0, mst,         \
                      lhi, sxr, aR, aZ, accN);                                \
        fetch_chunk(dstB + (uint32_t)sf * WSLICE,                             \
                    srcb + (size_t)qqf * 49152 + src_off);                    \
        if (++sf == NSLOT) sf = 0;                                            \
        if (++qqf == QSTEP) qqf = 0;                                          \
        if (++sc == NSLOT) sc = 0;                                            \
    }

    for (int t = 0; t < T_; t++) {
        // issue x_{t+1} loads early
        float4 vx0, vx1;
        if (tid < 256 && t + 1 < T_) {
            const float* xp = xbase + (size_t)(t + 1) * D_;
            vx0 = *reinterpret_cast<const float4*>(xp);
            vx1 = *reinterpret_cast<const float4*>(xp + 4);
        }

        // ---- Layer 1 gemm: chunks 0..9 ----
        zero4(aR, aZ, aNi, aNh);
#pragma unroll 1
        for (int q = 0; q < 2; q++) CONSUME(a_x, (uint32_t)(2 * q), 2048u, aNi);
#pragma unroll 1
        for (int q = 0; q < 8; q++) CONSUME(a_h1, (uint32_t)(2 * q), 8192u, aNh);
        __syncthreads();                 // x16 + h16_1 reads done
        if (tid < 256 && t + 1 < T_) {   // park x_{t+1} (x16 free now)
            uint4 p;
            p.x = pkh(vx0.x, vx0.y); p.y = pkh(vx0.z, vx0.w);
            p.z = pkh(vx1.x, vx1.y); p.w = pkh(vx1.z, vx1.w);
            *reinterpret_cast<uint4*>(x16 + xoff) = p;
        }
        epilogue(aR, aZ, aNi, aNh, h1r, h16_1, sB1, w, g, tig);
        __syncthreads();                 // h16_1 visible

        // ---- Layer 2 gemm: chunks 10..25 ----
        zero4(aR, aZ, aNi, aNh);
#pragma unroll 1
        for (int q = 0; q < 8; q++) CONSUME(a_h1, (uint32_t)(2 * q), 8192u, aNi);
#pragma unroll 1
        for (int q = 0; q < 8; q++) CONSUME(a_h2, (uint32_t)(2 * q), 8192u, aNh);
        __syncthreads();                 // h16_2 reads done
        epilogue(aR, aZ, aNi, aNh, h2r, h16_2, sB2, w, g, tig);
        __syncthreads();                 // h16_2 visible

        // ---- Head (warps 0-7) ----
        if (w < 8) {
            float aF[2][4];
#pragma unroll
            for (int m = 0; m < 2; m++)
#pragma unroll
                for (int q = 0; q < 4; q++) aF[m][q] = 0.f;
            gemmH(a_h2, bF, lhi, sxr, aF);
            int d0 = (w & 7) * 8 + 2 * tig;
            float bs0 = sBf[d0], bs1 = sBf[d0 + 1];
#pragma unroll
            for (int m = 0; m < 2; m++) {
                int r0 = g + m * 16, r1 = g + 8 + m * 16;
                float2 v;
                v.x = aF[m][0] + bs0; v.y = aF[m][1] + bs1;
                *reinterpret_cast<float2*>(
                    out + ((size_t)(b0 + r0) * T_ + t) * D_ + d0) = v;
                v.x = aF[m][2] + bs0; v.y = aF[m][3] + bs1;
                *reinterpret_cast<float2*>(
                    out + ((size_t)(b0 + r1) * T_ + t) * D_ + d0) = v;
            }
        }
    }
#undef CONSUME

    // final states from registers
    {
        size_t base = (size_t)B_ * T_ * D_;
        size_t base2 = base + (size_t)B_ * H_;
#pragma unroll
        for (int jt = 0; jt < 2; jt++)
#pragma unroll
            for (int m = 0; m < 2; m++)
#pragma unroll
                for (int hq = 0; hq < 2; hq++) {
                    int row = g + hq * 8 + m * 16;
                    int j0 = w * 16 + jt * 8 + 2 * tig;
                    float2 v1, v2;
                    v1.x = h1r[jt][m][hq][0]; v1.y = h1r[jt][m][hq][1];
                    v2.x = h2r[jt][m][hq][0]; v2.y = h2r[jt][m][hq][1];
                    *reinterpret_cast<float2*>(
                        out + base + (size_t)(b0 + row) * H_ + j0) = v1;
                    *reinterpret_cast<float2*>(
                        out + base2 + (size_t)(b0 + row) * H_ + j0) = v2;
                }
    }
}

// ---------------------------------------------------------------------------
extern "C" void kernel_launch(void* const* d_in, const int* in_sizes, int n_in,
                              void* d_out, int out_size) {
    (void)in_sizes; (void)n_in; (void)out_size;
    const float* x     = (const float*)d_in[0];
    const float* h1    = (const float*)d_in[1];
    const float* h2    = (const float*)d_in[2];
    const float* W_ih1 = (const float*)d_in[3];
    const float* W_hh1 = (const float*)d_in[4];
    const float* b_ih1 = (const float*)d_in[5];
    const float* b_hh1 = (const float*)d_in[6];
    const float* W_ih2 = (const float*)d_in[7];
    const float* W_hh2 = (const float*)d_in[8];
    const float* b_ih2 = (const float*)d_in[9];
    const float* b_hh2 = (const float*)d_in[10];
    const float* W_fc  = (const float*)d_in[11];
    const float* b_fc  = (const float*)d_in[12];
    float* out = (float*)d_out;

    repack_w<<<312, 256>>>(W_ih1, W_hh1, W_ih2, W_hh2);
    repack_head<<<8, 256>>>(W_fc);

    cudaFuncSetAttribute(gru_main, cudaFuncAttributeMaxDynamicSharedMemorySize,
                         SMEM_TOT);

    gru_main<<<NBLK, NTHR, SMEM_TOT>>>(x, h1, h2, b_ih1, b_hh1, b_ih2, b_hh2,
                                       b_fc, out);
}

// round 12
// speedup vs baseline: 1.0001x; 1.0001x over previous
#include <cuda_runtime.h>
#include <cuda_fp16.h>
#include <stdint.h>

#define B_    4096
#define T_    256
#define D_    64
#define H_    256
#define NBLK  128
#define MTILE 32
#define NTHR  512          // 16 compute warps; every warp also fetches its own weights

#define NSLOT 3            // per-warp smem ring slots
#define WSLICE 3072        // bytes per warp per k32 chunk (2 k16 x 6 frags x 32 lanes x 8B)
#define QSTEP 26           // k32 chunks per timestep: L1(2+8) + L2(8+8)

// Gate weights, chunk-major: [q 0..25][w 0..15][k16 0..1][t 0..5][lane] uint2
__device__ __align__(16) uint2 g_bW[QSTEP * 16 * 2 * 6 * 32];
// Head weights (tiny, direct-LDG path)
__device__ __align__(16) uint4 g_bF[8 * 8 * 32 + 512];

// SMEM layout (bytes)
#define OFF_RING  0                 // 16 warps x 3 slots x 3072 = 147456
#define OFF_H16A  147456            // fp16 h1: 16384 (single buffer, in-place)
#define OFF_H16B  163840            // fp16 h2: 16384
#define OFF_X16   180224            // fp16 x : 4096
#define OFF_SB1   184320            // 4*256 f32
#define OFF_SB2   188416
#define OFF_SBF   192512            // 64 f32
#define SMEM_TOT  192768

__device__ __forceinline__ uint32_t pkh(float a, float b) {
    __half2 h = __floats2half2_rn(a, b);
    return *reinterpret_cast<uint32_t*>(&h);
}
__device__ __forceinline__ void mma16(float* d, const uint32_t* a,
                                      uint32_t b0, uint32_t b1) {
    asm volatile(
        "mma.sync.aligned.m16n8k16.row.col.f32.f16.f16.f32 "
        "{%0,%1,%2,%3}, {%4,%5,%6,%7}, {%8,%9}, {%0,%1,%2,%3};\n"
        : "+f"(d[0]), "+f"(d[1]), "+f"(d[2]), "+f"(d[3])
        : "r"(a[0]), "r"(a[1]), "r"(a[2]), "r"(a[3]), "r"(b0), "r"(b1));
}
__device__ __forceinline__ void ldsm4(uint32_t* r, uint32_t addr) {
    asm volatile("ldmatrix.sync.aligned.m8n8.x4.shared.b16 {%0,%1,%2,%3}, [%4];"
                 : "=r"(r[0]), "=r"(r[1]), "=r"(r[2]), "=r"(r[3]) : "r"(addr));
}
__device__ __forceinline__ float ftanh(float x) {
    float y; asm("tanh.approx.f32 %0, %1;" : "=f"(y) : "f"(x)); return y;
}
__device__ __forceinline__ float fsig(float x) {
    return fmaf(0.5f, ftanh(0.5f * x), 0.5f);
}
__device__ __forceinline__ uint32_t cvta_s(const void* p) {
    return (uint32_t)__cvta_generic_to_shared(p);
}

// ---------------------------------------------------------------------------
// Repack gate weights, chunk-major for per-warp cp.async slices.
// k16 index kk = q*2 + hh:  kk<4: Wih1(K=64,k0=16kk); kk<20: Whh1;
//                           kk<36: Wih2; else Whh2.
__global__ void repack_w(const float* __restrict__ Wih1,
                         const float* __restrict__ Whh1,
                         const float* __restrict__ Wih2,
                         const float* __restrict__ Whh2) {
    int total = QSTEP * 16 * 2 * 6 * 32;
    for (int o = blockIdx.x * blockDim.x + threadIdx.x; o < total;
         o += gridDim.x * blockDim.x) {
        int lane = o & 31, r = o >> 5;
        int t = r % 6; r /= 6;
        int hh = r & 1; r >>= 1;
        int w = r & 15; r >>= 4;
        int q = r;                       // 0..25
        int kk = q * 2 + hh;             // global k16 index
        int G = t >> 1, jt = t & 1, g = lane >> 2, tig = lane & 3;
        int n = G * H_ + w * 16 + jt * 8 + g;
        const float* W; int K, k0;
        if (kk < 4)       { W = Wih1; K = 64;  k0 = kk * 16; }
        else if (kk < 20) { W = Whh1; K = 256; k0 = (kk - 4) * 16; }
        else if (kk < 36) { W = Wih2; K = 256; k0 = (kk - 20) * 16; }
        else              { W = Whh2; K = 256; k0 = (kk - 36) * 16; }
        const float* src = W + (size_t)n * K + k0 + 2 * tig;
        uint2 v;
        v.x = pkh(src[0], src[1]);
        v.y = pkh(src[8], src[9]);
        g_bW[o] = v;
    }
}
__global__ void repack_head(const float* __restrict__ W) {
    int total = 8 * 8 * 32;
    for (int o = blockIdx.x * blockDim.x + threadIdx.x; o < total;
         o += gridDim.x * blockDim.x) {
        int lane = o & 31, s = o >> 5;
        int c2 = s & 7, w = s >> 3;
        int g = lane >> 2, tig = lane & 3;
        int n = w * 8 + g;
        const float* src = W + (size_t)n * 256 + c2 * 32 + 2 * tig;
        uint4 v;
        v.x = pkh(src[0],  src[1]);
        v.y = pkh(src[8],  src[9]);
        v.z = pkh(src[16], src[17]);
        v.w = pkh(src[24], src[25]);
        g_bF[o] = v;
    }
}

// ---------------------------------------------------------------------------
// Warp-local weight fetch: copy this warp's 3KB slice of chunk qq into slot.
__device__ __forceinline__ void fetch_chunk(uint32_t dst, const char* src) {
#pragma unroll
    for (int i = 0; i < 6; i++)
        asm volatile("cp.async.cg.shared.global [%0], [%1], 16;"
                     :: "r"(dst + (uint32_t)(i * 16)), "l"(src + i * 16));
    asm volatile("cp.async.commit_group;" ::: "memory");
}

// Consume one k32 chunk from my ring slot: 4 ldmatrix (A), 12 LDS.64 (B),
// 24 MMAs. slotB has lane*8 folded in.
__device__ __forceinline__ void consume_chunk(
    uint32_t slotB, uint32_t aBase, uint32_t kk0, uint32_t mst,
    int lhi, int sxr,
    float (&aR)[2][2][4], float (&aZ)[2][2][4], float (&aN)[2][2][4]) {
#pragma unroll
    for (int hh = 0; hh < 2; hh++) {
        uint32_t cc = (kk0 + (uint32_t)hh) * 2 + (uint32_t)lhi;
        uint32_t a0 = aBase + ((cc ^ (uint32_t)sxr) << 4);
        uint32_t af0[4], af1[4];
        ldsm4(af0, a0);
        ldsm4(af1, a0 + mst);
        uint32_t wb = slotB + (uint32_t)(hh * 1536);
#pragma unroll
        for (int t = 0; t < 6; t++) {
            uint32_t w0, w1;
            asm volatile("ld.shared.v2.u32 {%0,%1}, [%2];"
                         : "=r"(w0), "=r"(w1) : "r"(wb + (uint32_t)(t * 256)));
            float (*acc)[2][4] = (t < 2) ? aR : (t < 4) ? aZ : aN;
            int jt = t & 1;
            mma16(acc[jt][0], af0, w0, w1);
            mma16(acc[jt][1], af1, w0, w1);
        }
    }
}

// Head GEMM (warps 0-7): direct LDG of g_bF, K=256.
__device__ __forceinline__ void gemmH(uint32_t ah,
                                      const uint4* __restrict__ blobWL,
                                      int lhi, int sxr, float (&acc)[2][4]) {
    uint4 buf[8];
#pragma unroll
    for (int i = 0; i < 8; i++) buf[i] = blobWL[i * 32];
#pragma unroll 1
    for (int c2 = 0; c2 < 8; c2++) {
        uint32_t af[2][2][4];
#pragma unroll
        for (int m = 0; m < 2; m++)
#pragma unroll
            for (int ch = 0; ch < 2; ch++) {
                int cc = c2 * 4 + ch * 2 + lhi;
                uint32_t addr = (m ? ah + 16 * 512 : ah) +
                                (uint32_t)((cc ^ sxr) << 4);
                ldsm4(af[m][ch], addr);
            }
        uint4 wv = buf[c2];
        mma16(acc[0], af[0][0], wv.x, wv.y);
        mma16(acc[1], af[1][0], wv.x, wv.y);
        mma16(acc[0], af[0][1], wv.z, wv.w);
        mma16(acc[1], af[1][1], wv.z, wv.w);
    }
}

__device__ __forceinline__ void zero4(float (&aR)[2][2][4], float (&aZ)[2][2][4],
                                      float (&aNi)[2][2][4],
                                      float (&aNh)[2][2][4]) {
#pragma unroll
    for (int jt = 0; jt < 2; jt++)
#pragma unroll
        for (int m = 0; m < 2; m++)
#pragma unroll
            for (int q = 0; q < 4; q++) {
                aR[jt][m][q] = 0.f; aZ[jt][m][q] = 0.f;
                aNi[jt][m][q] = 0.f; aNh[jt][m][q] = 0.f;
            }
}

// GRU gate math; fp32 h lives in REGISTERS (hr, thread-private, fixed cells),
// fp16 h' written in place to h16 (callers barrier around it).
__device__ __forceinline__ void epilogue(float (&aR)[2][2][4], float (&aZ)[2][2][4],
                                         float (&aNi)[2][2][4],
                                         float (&aNh)[2][2][4],
                                         float (&hr)[2][2][2][2], char* h16,
                                         const float* __restrict__ sB,
                                         int w, int g, int tig) {
#pragma unroll
    for (int jt = 0; jt < 2; jt++) {
        int j0 = w * 16 + jt * 8 + 2 * tig;
        float br0 = sB[j0],          br1 = sB[j0 + 1];
        float bz0 = sB[H_ + j0],     bz1 = sB[H_ + j0 + 1];
        float bi0 = sB[2 * H_ + j0], bi1 = sB[2 * H_ + j0 + 1];
        float bh0 = sB[3 * H_ + j0], bh1 = sB[3 * H_ + j0 + 1];
        int cc = 2 * w + jt;
#pragma unroll
        for (int m = 0; m < 2; m++)
#pragma unroll
            for (int hq = 0; hq < 2; hq++) {
                int row = g + hq * 8 + m * 16;
                int q0 = hq * 2, q1 = hq * 2 + 1;
                float hc0 = hr[jt][m][hq][0], hc1 = hr[jt][m][hq][1];
                float r0 = fsig(aR[jt][m][q0] + br0);
                float r1 = fsig(aR[jt][m][q1] + br1);
                float z0 = fsig(aZ[jt][m][q0] + bz0);
                float z1 = fsig(aZ[jt][m][q1] + bz1);
                float n0 = ftanh(aNi[jt][m][q0] + bi0 + r0 * (aNh[jt][m][q0] + bh0));
                float n1 = ftanh(aNi[jt][m][q1] + bi1 + r1 * (aNh[jt][m][q1] + bh1));
                float h0 = (1.f - z0) * n0 + z0 * hc0;
                float h1 = (1.f - z1) * n1 + z1 * hc1;
                hr[jt][m][hq][0] = h0;
                hr[jt][m][hq][1] = h1;
                *reinterpret_cast<__half2*>(
                    h16 + row * 512 + ((cc ^ (row & 7)) << 4) + tig * 4) =
                    __floats2half2_rn(h0, h1);
            }
    }
}

// ---------------------------------------------------------------------------
extern __shared__ __align__(1024) char smem[];

__global__ void __launch_bounds__(NTHR, 1)
gru_main(const float* __restrict__ x, const float* __restrict__ h1g,
         const float* __restrict__ h2g,
         const float* __restrict__ bih1, const float* __restrict__ bhh1,
         const float* __restrict__ bih2, const float* __restrict__ bhh2,
         const float* __restrict__ bfc, float* __restrict__ out) {
    char*  h16_1 = smem + OFF_H16A;
    char*  h16_2 = smem + OFF_H16B;
    char*  x16   = smem + OFF_X16;
    float* sB1   = (float*)(smem + OFF_SB1);
    float* sB2   = (float*)(smem + OFF_SB2);
    float* sBf   = (float*)(smem + OFF_SBF);

    const int tid = threadIdx.x;
    const int w = tid >> 5, lane = tid & 31, g = lane >> 2, tig = lane & 3;
    const int l16 = lane & 15, lhi = lane >> 4, sxr = l16 & 7;
    const int b0 = blockIdx.x * MTILE;

    // combined biases into shared
    if (tid < 256) {
        sB1[tid]          = bih1[tid] + bhh1[tid];
        sB1[H_ + tid]     = bih1[H_ + tid] + bhh1[H_ + tid];
        sB1[2 * H_ + tid] = bih1[2 * H_ + tid];
        sB1[3 * H_ + tid] = bhh1[2 * H_ + tid];
        sB2[tid]          = bih2[tid] + bhh2[tid];
        sB2[H_ + tid]     = bih2[H_ + tid] + bhh2[H_ + tid];
        sB2[2 * H_ + tid] = bih2[2 * H_ + tid];
        sB2[3 * H_ + tid] = bhh2[2 * H_ + tid];
        if (tid < D_) sBf[tid] = bfc[tid];

        // initial fp16 h (swizzled)
        int cc = tid >> 3, cb = tid & 7;
        for (int i = 0; i < MTILE; i++) {
            float v1 = h1g[(size_t)(b0 + i) * H_ + tid];
            float v2 = h2g[(size_t)(b0 + i) * H_ + tid];
            int off = i * 512 + ((cc ^ (i & 7)) << 4) + cb * 2;
            *reinterpret_cast<__half*>(h16_1 + off) = __float2half_rn(v1);
            *reinterpret_cast<__half*>(h16_2 + off) = __float2half_rn(v2);
        }
    }

    // fp32 h in registers: hr[jt][m][hq][c] at row = g+hq*8+m*16,
    // col = w*16+jt*8+2*tig+c  (thread-private, fixed across steps)
    float h1r[2][2][2][2], h2r[2][2][2][2];
#pragma unroll
    for (int jt = 0; jt < 2; jt++)
#pragma unroll
        for (int m = 0; m < 2; m++)
#pragma unroll
            for (int hq = 0; hq < 2; hq++) {
                int row = g + hq * 8 + m * 16;
                int j0 = w * 16 + jt * 8 + 2 * tig;
                float2 v1 = *reinterpret_cast<const float2*>(
                    h1g + (size_t)(b0 + row) * H_ + j0);
                float2 v2 = *reinterpret_cast<const float2*>(
                    h2g + (size_t)(b0 + row) * H_ + j0);
                h1r[jt][m][hq][0] = v1.x; h1r[jt][m][hq][1] = v1.y;
                h2r[jt][m][hq][0] = v2.x; h2r[jt][m][hq][1] = v2.y;
            }

    // x staging (threads 0..255)
    const int xr = (tid & 255) >> 3, xcc = tid & 7;
    const float* xbase = x + ((size_t)(b0 + xr) * T_) * D_ + xcc * 8;
    const int xoff = xr * 128 + ((xcc ^ (xr & 7)) << 4);
    if (tid < 256) {
        float4 v0 = *reinterpret_cast<const float4*>(xbase);
        float4 v1 = *reinterpret_cast<const float4*>(xbase + 4);
        uint4 p;
        p.x = pkh(v0.x, v0.y); p.y = pkh(v0.z, v0.w);
        p.z = pkh(v1.x, v1.y); p.w = pkh(v1.z, v1.w);
        *reinterpret_cast<uint4*>(x16 + xoff) = p;
    }

    // shared addresses
    const uint32_t ringS = cvta_s(smem + OFF_RING);
    const uint32_t a_h1 = cvta_s(h16_1) + l16 * 512;
    const uint32_t a_h2 = cvta_s(h16_2) + l16 * 512;
    const uint32_t a_x  = cvta_s(x16) + l16 * 128;
    const uint4* bF = g_bF + (size_t)(w & 7) * 8 * 32 + lane;

    // per-warp weight stream state
    const char* srcb = (const char*)g_bW;
    const uint32_t src_off = (uint32_t)w * WSLICE + (uint32_t)lane * 96;
    const uint32_t dstB = ringS + (uint32_t)w * (NSLOT * WSLICE) +
                          (uint32_t)lane * 96;
    const uint32_t slotB = ringS + (uint32_t)w * (NSLOT * WSLICE) +
                           (uint32_t)lane * 8;

    int qqf = 0, sf = 0, sc = 0;
    // warm the per-warp ring with 2 chunks in flight
    fetch_chunk(dstB, srcb + src_off);                       // chunk 0 -> slot 0
    fetch_chunk(dstB + WSLICE, srcb + 49152 + src_off);      // chunk 1 -> slot 1
    qqf = 2; sf = 2;

    __syncthreads();

    float aR[2][2][4], aZ[2][2][4], aNi[2][2][4], aNh[2][2][4];

#define CONSUME(aBase, kk0, mst, accN)                                        \
    {                                                                         \
        asm volatile("cp.async.wait_group 1;" ::: "memory");                  \
        __syncwarp();                                                         \
        consume_chunk(slotB + (uint32_t)sc * WSLICE, aBase, kk0, mst,         \
                      lhi, sxr, aR, aZ, accN);                                \
        fetch_chunk(dstB + (uint32_t)sf * WSLICE,                             \
                    srcb + (size_t)qqf * 49152 + src_off);                    \
        if (++sf == NSLOT) sf = 0;                                            \
        if (++qqf == QSTEP) qqf = 0;                                          \
        if (++sc == NSLOT) sc = 0;                                            \
    }

    for (int t = 0; t < T_; t++) {
        // issue x_{t+1} loads early
        float4 vx0, vx1;
        if (tid < 256 && t + 1 < T_) {
            const float* xp = xbase + (size_t)(t + 1) * D_;
            vx0 = *reinterpret_cast<const float4*>(xp);
            vx1 = *reinterpret_cast<const float4*>(xp + 4);
        }

        // ---- Layer 1 gemm: chunks 0..9 ----
        zero4(aR, aZ, aNi, aNh);
#pragma unroll 1
        for (int q = 0; q < 2; q++) CONSUME(a_x, (uint32_t)(2 * q), 2048u, aNi);
#pragma unroll 1
        for (int q = 0; q < 8; q++) CONSUME(a_h1, (uint32_t)(2 * q), 8192u, aNh);
        __syncthreads();                 // x16 + h16_1 reads done
        if (tid < 256 && t + 1 < T_) {   // park x_{t+1} (x16 free now)
            uint4 p;
            p.x = pkh(vx0.x, vx0.y); p.y = pkh(vx0.z, vx0.w);
            p.z = pkh(vx1.x, vx1.y); p.w = pkh(vx1.z, vx1.w);
            *reinterpret_cast<uint4*>(x16 + xoff) = p;
        }
        epilogue(aR, aZ, aNi, aNh, h1r, h16_1, sB1, w, g, tig);
        __syncthreads();                 // h16_1 visible

        // ---- Layer 2 gemm: chunks 10..25 ----
        zero4(aR, aZ, aNi, aNh);
#pragma unroll 1
        for (int q = 0; q < 8; q++) CONSUME(a_h1, (uint32_t)(2 * q), 8192u, aNi);
#pragma unroll 1
        for (int q = 0; q < 8; q++) CONSUME(a_h2, (uint32_t)(2 * q), 8192u, aNh);
        __syncthreads();                 // h16_2 reads done
        epilogue(aR, aZ, aNi, aNh, h2r, h16_2, sB2, w, g, tig);
        __syncthreads();                 // h16_2 visible

        // ---- Head (warps 0-7) ----
        if (w < 8) {
            float aF[2][4];
#pragma unroll
            for (int m = 0; m < 2; m++)
#pragma unroll
                for (int q = 0; q < 4; q++) aF[m][q] = 0.f;
            gemmH(a_h2, bF, lhi, sxr, aF);
            int d0 = (w & 7) * 8 + 2 * tig;
            float bs0 = sBf[d0], bs1 = sBf[d0 + 1];
#pragma unroll
            for (int m = 0; m < 2; m++) {
                int r0 = g + m * 16, r1 = g + 8 + m * 16;
                float2 v;
                v.x = aF[m][0] + bs0; v.y = aF[m][1] + bs1;
                *reinterpret_cast<float2*>(
                    out + ((size_t)(b0 + r0) * T_ + t) * D_ + d0) = v;
                v.x = aF[m][2] + bs0; v.y = aF[m][3] + bs1;
                *reinterpret_cast<float2*>(
                    out + ((size_t)(b0 + r1) * T_ + t) * D_ + d0) = v;
            }
        }
    }
#undef CONSUME

    // final states from registers
    {
        size_t base = (size_t)B_ * T_ * D_;
        size_t base2 = base + (size_t)B_ * H_;
#pragma unroll
        for (int jt = 0; jt < 2; jt++)
#pragma unroll
            for (int m = 0; m < 2; m++)
#pragma unroll
                for (int hq = 0; hq < 2; hq++) {
                    int row = g + hq * 8 + m * 16;
                    int j0 = w * 16 + jt * 8 + 2 * tig;
                    float2 v1, v2;
                    v1.x = h1r[jt][m][hq][0]; v1.y = h1r[jt][m][hq][1];
                    v2.x = h2r[jt][m][hq][0]; v2.y = h2r[jt][m][hq][1];
                    *reinterpret_cast<float2*>(
                        out + base + (size_t)(b0 + row) * H_ + j0) = v1;
                    *reinterpret_cast<float2*>(
                        out + base2 + (size_t)(b0 + row) * H_ + j0) = v2;
                }
    }
}

// ---------------------------------------------------------------------------
extern "C" void kernel_launch(void* const* d_in, const int* in_sizes, int n_in,
                              void* d_out, int out_size) {
    (void)in_sizes; (void)n_in; (void)out_size;
    const float* x     = (const float*)d_in[0];
    const float* h1    = (const float*)d_in[1];
    const float* h2    = (const float*)d_in[2];
    const float* W_ih1 = (const float*)d_in[3];
    const float* W_hh1 = (const float*)d_in[4];
    const float* b_ih1 = (const float*)d_in[5];
    const float* b_hh1 = (const float*)d_in[6];
    const float* W_ih2 = (const float*)d_in[7];
    const float* W_hh2 = (const float*)d_in[8];
    const float* b_ih2 = (const float*)d_in[9];
    const float* b_hh2 = (const float*)d_in[10];
    const float* W_fc  = (const float*)d_in[11];
    const float* b_fc  = (const float*)d_in[12];
    float* out = (float*)d_out;

    repack_w<<<312, 256>>>(W_ih1, W_hh1, W_ih2, W_hh2);
    repack_head<<<8, 256>>>(W_fc);

    cudaFuncSetAttribute(gru_main, cudaFuncAttributeMaxDynamicSharedMemorySize,
                         SMEM_TOT);

    gru_main<<<NBLK, NTHR, SMEM_TOT>>>(x, h1, h2, b_ih1, b_hh1, b_ih2, b_hh2,
                                       b_fc, out);
}

// round 13
// speedup vs baseline: 1.0011x; 1.0010x over previous
#include <cuda_runtime.h>
#include <cuda_fp16.h>
#include <stdint.h>

#define B_    4096
#define T_    256
#define D_    64
#define H_    256
#define NBLK  128
#define MTILE 32
#define NTHR  512          // 16 compute warps; every warp also fetches its own weights

#define NSLOT 3            // per-warp smem ring slots
#define WSLICE 3072        // bytes per warp per k32 chunk (2 k16 x 6 frags x 32 lanes x 8B)
#define QSTEP 26           // k32 chunks per timestep: L1(2+8) + L2(8+8)

// Gate weights, chunk-major: [q 0..25][w 0..15][k16 0..1][t 0..5][lane] uint2
__device__ __align__(16) uint2 g_bW[QSTEP * 16 * 2 * 6 * 32];
// Head weights (tiny, direct-LDG path)
__device__ __align__(16) uint4 g_bF[8 * 8 * 32 + 512];

// SMEM layout (bytes)
#define OFF_RING  0                 // 16 warps x 3 slots x 3072 = 147456
#define OFF_H16A  147456            // fp16 h1: 16384 (single buffer, in-place)
#define OFF_H16B  163840            // fp16 h2: 16384
#define OFF_X16   180224            // fp16 x : 4096
#define OFF_SB1   184320            // 4*256 f32
#define OFF_SB2   188416
#define OFF_SBF   192512            // 64 f32
#define SMEM_TOT  192768

__device__ __forceinline__ uint32_t pkh(float a, float b) {
    __half2 h = __floats2half2_rn(a, b);
    return *reinterpret_cast<uint32_t*>(&h);
}
__device__ __forceinline__ void mma16(float* d, const uint32_t* a,
                                      uint32_t b0, uint32_t b1) {
    asm volatile(
        "mma.sync.aligned.m16n8k16.row.col.f32.f16.f16.f32 "
        "{%0,%1,%2,%3}, {%4,%5,%6,%7}, {%8,%9}, {%0,%1,%2,%3};\n"
        : "+f"(d[0]), "+f"(d[1]), "+f"(d[2]), "+f"(d[3])
        : "r"(a[0]), "r"(a[1]), "r"(a[2]), "r"(a[3]), "r"(b0), "r"(b1));
}
__device__ __forceinline__ void ldsm4(uint32_t* r, uint32_t addr) {
    asm volatile("ldmatrix.sync.aligned.m8n8.x4.shared.b16 {%0,%1,%2,%3}, [%4];"
                 : "=r"(r[0]), "=r"(r[1]), "=r"(r[2]), "=r"(r[3]) : "r"(addr));
}
__device__ __forceinline__ float ftanh(float x) {
    float y; asm("tanh.approx.f32 %0, %1;" : "=f"(y) : "f"(x)); return y;
}
__device__ __forceinline__ float fsig(float x) {
    return fmaf(0.5f, ftanh(0.5f * x), 0.5f);
}
__device__ __forceinline__ uint32_t cvta_s(const void* p) {
    return (uint32_t)__cvta_generic_to_shared(p);
}

// ---------------------------------------------------------------------------
// Repack gate weights, chunk-major for per-warp cp.async slices.
// k16 index kk = q*2 + hh:  kk<4: Wih1(K=64,k0=16kk); kk<20: Whh1;
//                           kk<36: Wih2; else Whh2.
__global__ void repack_w(const float* __restrict__ Wih1,
                         const float* __restrict__ Whh1,
                         const float* __restrict__ Wih2,
                         const float* __restrict__ Whh2) {
    int total = QSTEP * 16 * 2 * 6 * 32;
    for (int o = blockIdx.x * blockDim.x + threadIdx.x; o < total;
         o += gridDim.x * blockDim.x) {
        int lane = o & 31, r = o >> 5;
        int t = r % 6; r /= 6;
        int hh = r & 1; r >>= 1;
        int w = r & 15; r >>= 4;
        int q = r;                       // 0..25
        int kk = q * 2 + hh;             // global k16 index
        int G = t >> 1, jt = t & 1, g = lane >> 2, tig = lane & 3;
        int n = G * H_ + w * 16 + jt * 8 + g;
        const float* W; int K, k0;
        if (kk < 4)       { W = Wih1; K = 64;  k0 = kk * 16; }
        else if (kk < 20) { W = Whh1; K = 256; k0 = (kk - 4) * 16; }
        else if (kk < 36) { W = Wih2; K = 256; k0 = (kk - 20) * 16; }
        else              { W = Whh2; K = 256; k0 = (kk - 36) * 16; }
        const float* src = W + (size_t)n * K + k0 + 2 * tig;
        uint2 v;
        v.x = pkh(src[0], src[1]);
        v.y = pkh(src[8], src[9]);
        g_bW[o] = v;
    }
}
__global__ void repack_head(const float* __restrict__ W) {
    int total = 8 * 8 * 32;
    for (int o = blockIdx.x * blockDim.x + threadIdx.x; o < total;
         o += gridDim.x * blockDim.x) {
        int lane = o & 31, s = o >> 5;
        int c2 = s & 7, w = s >> 3;
        int g = lane >> 2, tig = lane & 3;
        int n = w * 8 + g;
        const float* src = W + (size_t)n * 256 + c2 * 32 + 2 * tig;
        uint4 v;
        v.x = pkh(src[0],  src[1]);
        v.y = pkh(src[8],  src[9]);
        v.z = pkh(src[16], src[17]);
        v.w = pkh(src[24], src[25]);
        g_bF[o] = v;
    }
}

// ---------------------------------------------------------------------------
// Warp-local weight fetch: copy this warp's 3KB slice of chunk qq into slot.
__device__ __forceinline__ void fetch_chunk(uint32_t dst, const char* src) {
#pragma unroll
    for (int i = 0; i < 6; i++)
        asm volatile("cp.async.cg.shared.global [%0], [%1], 16;"
                     :: "r"(dst + (uint32_t)(i * 16)), "l"(src + i * 16));
    asm volatile("cp.async.commit_group;" ::: "memory");
}

// Consume one k32 chunk from my ring slot: 4 ldmatrix (A), 12 LDS.64 (B),
// 24 MMAs. slotB has lane*8 folded in.
__device__ __forceinline__ void consume_chunk(
    uint32_t slotB, uint32_t aBase, uint32_t kk0, uint32_t mst,
    int lhi, int sxr,
    float (&aR)[2][2][4], float (&aZ)[2][2][4], float (&aN)[2][2][4]) {
#pragma unroll
    for (int hh = 0; hh < 2; hh++) {
        uint32_t cc = (kk0 + (uint32_t)hh) * 2 + (uint32_t)lhi;
        uint32_t a0 = aBase + ((cc ^ (uint32_t)sxr) << 4);
        uint32_t af0[4], af1[4];
        ldsm4(af0, a0);
        ldsm4(af1, a0 + mst);
        uint32_t wb = slotB + (uint32_t)(hh * 1536);
#pragma unroll
        for (int t = 0; t < 6; t++) {
            uint32_t w0, w1;
            asm volatile("ld.shared.v2.u32 {%0,%1}, [%2];"
                         : "=r"(w0), "=r"(w1) : "r"(wb + (uint32_t)(t * 256)));
            float (*acc)[2][4] = (t < 2) ? aR : (t < 4) ? aZ : aN;
            int jt = t & 1;
            mma16(acc[jt][0], af0, w0, w1);
            mma16(acc[jt][1], af1, w0, w1);
        }
    }
}

// Head GEMM (warps 0-7): direct LDG of g_bF, K=256.
__device__ __forceinline__ void gemmH(uint32_t ah,
                                      const uint4* __restrict__ blobWL,
                                      int lhi, int sxr, float (&acc)[2][4]) {
    uint4 buf[8];
#pragma unroll
    for (int i = 0; i < 8; i++) buf[i] = blobWL[i * 32];
#pragma unroll 1
    for (int c2 = 0; c2 < 8; c2++) {
        uint32_t af[2][2][4];
#pragma unroll
        for (int m = 0; m < 2; m++)
#pragma unroll
            for (int ch = 0; ch < 2; ch++) {
                int cc = c2 * 4 + ch * 2 + lhi;
                uint32_t addr = (m ? ah + 16 * 512 : ah) +
                                (uint32_t)((cc ^ sxr) << 4);
                ldsm4(af[m][ch], addr);
            }
        uint4 wv = buf[c2];
        mma16(acc[0], af[0][0], wv.x, wv.y);
        mma16(acc[1], af[1][0], wv.x, wv.y);
        mma16(acc[0], af[0][1], wv.z, wv.w);
        mma16(acc[1], af[1][1], wv.z, wv.w);
    }
}

__device__ __forceinline__ void zero4(float (&aR)[2][2][4], float (&aZ)[2][2][4],
                                      float (&aNi)[2][2][4],
                                      float (&aNh)[2][2][4]) {
#pragma unroll
    for (int jt = 0; jt < 2; jt++)
#pragma unroll
        for (int m = 0; m < 2; m++)
#pragma unroll
            for (int q = 0; q < 4; q++) {
                aR[jt][m][q] = 0.f; aZ[jt][m][q] = 0.f;
                aNi[jt][m][q] = 0.f; aNh[jt][m][q] = 0.f;
            }
}

// GRU gate math; fp32 h lives in REGISTERS (hr, thread-private, fixed cells),
// fp16 h' written in place to h16 (callers barrier around it).
__device__ __forceinline__ void epilogue(float (&aR)[2][2][4], float (&aZ)[2][2][4],
                                         float (&aNi)[2][2][4],
                                         float (&aNh)[2][2][4],
                                         float (&hr)[2][2][2][2], char* h16,
                                         const float* __restrict__ sB,
                                         int w, int g, int tig) {
#pragma unroll
    for (int jt = 0; jt < 2; jt++) {
        int j0 = w * 16 + jt * 8 + 2 * tig;
        float br0 = sB[j0],          br1 = sB[j0 + 1];
        float bz0 = sB[H_ + j0],     bz1 = sB[H_ + j0 + 1];
        float bi0 = sB[2 * H_ + j0], bi1 = sB[2 * H_ + j0 + 1];
        float bh0 = sB[3 * H_ + j0], bh1 = sB[3 * H_ + j0 + 1];
        int cc = 2 * w + jt;
#pragma unroll
        for (int m = 0; m < 2; m++)
#pragma unroll
            for (int hq = 0; hq < 2; hq++) {
                int row = g + hq * 8 + m * 16;
                int q0 = hq * 2, q1 = hq * 2 + 1;
                float hc0 = hr[jt][m][hq][0], hc1 = hr[jt][m][hq][1];
                float r0 = fsig(aR[jt][m][q0] + br0);
                float r1 = fsig(aR[jt][m][q1] + br1);
                float z0 = fsig(aZ[jt][m][q0] + bz0);
                float z1 = fsig(aZ[jt][m][q1] + bz1);
                float n0 = ftanh(aNi[jt][m][q0] + bi0 + r0 * (aNh[jt][m][q0] + bh0));
                float n1 = ftanh(aNi[jt][m][q1] + bi1 + r1 * (aNh[jt][m][q1] + bh1));
                float h0 = (1.f - z0) * n0 + z0 * hc0;
                float h1 = (1.f - z1) * n1 + z1 * hc1;
                hr[jt][m][hq][0] = h0;
                hr[jt][m][hq][1] = h1;
                *reinterpret_cast<__half2*>(
                    h16 + row * 512 + ((cc ^ (row & 7)) << 4) + tig * 4) =
                    __floats2half2_rn(h0, h1);
            }
    }
}

// ---------------------------------------------------------------------------
extern __shared__ __align__(1024) char smem[];

__global__ void __launch_bounds__(NTHR, 1)
gru_main(const float* __restrict__ x, const float* __restrict__ h1g,
         const float* __restrict__ h2g,
         const float* __restrict__ bih1, const float* __restrict__ bhh1,
         const float* __restrict__ bih2, const float* __restrict__ bhh2,
         const float* __restrict__ bfc, float* __restrict__ out) {
    char*  h16_1 = smem + OFF_H16A;
    char*  h16_2 = smem + OFF_H16B;
    char*  x16   = smem + OFF_X16;
    float* sB1   = (float*)(smem + OFF_SB1);
    float* sB2   = (float*)(smem + OFF_SB2);
    float* sBf   = (float*)(smem + OFF_SBF);

    const int tid = threadIdx.x;
    const int w = tid >> 5, lane = tid & 31, g = lane >> 2, tig = lane & 3;
    const int l16 = lane & 15, lhi = lane >> 4, sxr = l16 & 7;
    const int b0 = blockIdx.x * MTILE;

    // combined biases into shared
    if (tid < 256) {
        sB1[tid]          = bih1[tid] + bhh1[tid];
        sB1[H_ + tid]     = bih1[H_ + tid] + bhh1[H_ + tid];
        sB1[2 * H_ + tid] = bih1[2 * H_ + tid];
        sB1[3 * H_ + tid] = bhh1[2 * H_ + tid];
        sB2[tid]          = bih2[tid] + bhh2[tid];
        sB2[H_ + tid]     = bih2[H_ + tid] + bhh2[H_ + tid];
        sB2[2 * H_ + tid] = bih2[2 * H_ + tid];
        sB2[3 * H_ + tid] = bhh2[2 * H_ + tid];
        if (tid < D_) sBf[tid] = bfc[tid];

        // initial fp16 h (swizzled)
        int cc = tid >> 3, cb = tid & 7;
        for (int i = 0; i < MTILE; i++) {
            float v1 = h1g[(size_t)(b0 + i) * H_ + tid];
            float v2 = h2g[(size_t)(b0 + i) * H_ + tid];
            int off = i * 512 + ((cc ^ (i & 7)) << 4) + cb * 2;
            *reinterpret_cast<__half*>(h16_1 + off) = __float2half_rn(v1);
            *reinterpret_cast<__half*>(h16_2 + off) = __float2half_rn(v2);
        }
    }

    // fp32 h in registers: hr[jt][m][hq][c] at row = g+hq*8+m*16,
    // col = w*16+jt*8+2*tig+c  (thread-private, fixed across steps)
    float h1r[2][2][2][2], h2r[2][2][2][2];
#pragma unroll
    for (int jt = 0; jt < 2; jt++)
#pragma unroll
        for (int m = 0; m < 2; m++)
#pragma unroll
            for (int hq = 0; hq < 2; hq++) {
                int row = g + hq * 8 + m * 16;
                int j0 = w * 16 + jt * 8 + 2 * tig;
                float2 v1 = *reinterpret_cast<const float2*>(
                    h1g + (size_t)(b0 + row) * H_ + j0);
                float2 v2 = *reinterpret_cast<const float2*>(
                    h2g + (size_t)(b0 + row) * H_ + j0);
                h1r[jt][m][hq][0] = v1.x; h1r[jt][m][hq][1] = v1.y;
                h2r[jt][m][hq][0] = v2.x; h2r[jt][m][hq][1] = v2.y;
            }

    // x staging (threads 0..255)
    const int xr = (tid & 255) >> 3, xcc = tid & 7;
    const float* xbase = x + ((size_t)(b0 + xr) * T_) * D_ + xcc * 8;
    const int xoff = xr * 128 + ((xcc ^ (xr & 7)) << 4);
    if (tid < 256) {
        float4 v0 = *reinterpret_cast<const float4*>(xbase);
        float4 v1 = *reinterpret_cast<const float4*>(xbase + 4);
        uint4 p;
        p.x = pkh(v0.x, v0.y); p.y = pkh(v0.z, v0.w);
        p.z = pkh(v1.x, v1.y); p.w = pkh(v1.z, v1.w);
        *reinterpret_cast<uint4*>(x16 + xoff) = p;
    }

    // shared addresses
    const uint32_t ringS = cvta_s(smem + OFF_RING);
    const uint32_t a_h1 = cvta_s(h16_1) + l16 * 512;
    const uint32_t a_h2 = cvta_s(h16_2) + l16 * 512;
    const uint32_t a_x  = cvta_s(x16) + l16 * 128;
    const uint4* bF = g_bF + (size_t)(w & 7) * 8 * 32 + lane;

    // per-warp weight stream state
    const char* srcb = (const char*)g_bW;
    const uint32_t src_off = (uint32_t)w * WSLICE + (uint32_t)lane * 96;
    const uint32_t dstB = ringS + (uint32_t)w * (NSLOT * WSLICE) +
                          (uint32_t)lane * 96;
    const uint32_t slotB = ringS + (uint32_t)w * (NSLOT * WSLICE) +
                           (uint32_t)lane * 8;

    int qqf = 0, sf = 0, sc = 0;
    // warm the per-warp ring with 2 chunks in flight
    fetch_chunk(dstB, srcb + src_off);                       // chunk 0 -> slot 0
    fetch_chunk(dstB + WSLICE, srcb + 49152 + src_off);      // chunk 1 -> slot 1
    qqf = 2; sf = 2;

    __syncthreads();

    float aR[2][2][4], aZ[2][2][4], aNi[2][2][4], aNh[2][2][4];

#define CONSUME(aBase, kk0, mst, accN)                                        \
    {                                                                         \
        asm volatile("cp.async.wait_group 1;" ::: "memory");                  \
        __syncwarp();                                                         \
        consume_chunk(slotB + (uint32_t)sc * WSLICE, aBase, kk0, mst,         \
                      lhi, sxr, aR, aZ, accN);                                \
        fetch_chunk(dstB + (uint32_t)sf * WSLICE,                             \
                    srcb + (size_t)qqf * 49152 + src_off);                    \
        if (++sf == NSLOT) sf = 0;                                            \
        if (++qqf == QSTEP) qqf = 0;                                          \
        if (++sc == NSLOT) sc = 0;                                            \
    }

    for (int t = 0; t < T_; t++) {
        // issue x_{t+1} loads early
        float4 vx0, vx1;
        if (tid < 256 && t + 1 < T_) {
            const float* xp = xbase + (size_t)(t + 1) * D_;
            vx0 = *reinterpret_cast<const float4*>(xp);
            vx1 = *reinterpret_cast<const float4*>(xp + 4);
        }

        // ---- Layer 1 gemm: chunks 0..9 ----
        zero4(aR, aZ, aNi, aNh);
#pragma unroll 1
        for (int q = 0; q < 2; q++) CONSUME(a_x, (uint32_t)(2 * q), 2048u, aNi);
#pragma unroll 1
        for (int q = 0; q < 8; q++) CONSUME(a_h1, (uint32_t)(2 * q), 8192u, aNh);
        __syncthreads();                 // x16 + h16_1 reads done
        if (tid < 256 && t + 1 < T_) {   // park x_{t+1} (x16 free now)
            uint4 p;
            p.x = pkh(vx0.x, vx0.y); p.y = pkh(vx0.z, vx0.w);
            p.z = pkh(vx1.x, vx1.y); p.w = pkh(vx1.z, vx1.w);
            *reinterpret_cast<uint4*>(x16 + xoff) = p;
        }
        epilogue(aR, aZ, aNi, aNh, h1r, h16_1, sB1, w, g, tig);
        __syncthreads();                 // h16_1 visible

        // ---- Layer 2 gemm: chunks 10..25 ----
        zero4(aR, aZ, aNi, aNh);
#pragma unroll 1
        for (int q = 0; q < 8; q++) CONSUME(a_h1, (uint32_t)(2 * q), 8192u, aNi);
#pragma unroll 1
        for (int q = 0; q < 8; q++) CONSUME(a_h2, (uint32_t)(2 * q), 8192u, aNh);
        __syncthreads();                 // h16_2 reads done
        epilogue(aR, aZ, aNi, aNh, h2r, h16_2, sB2, w, g, tig);
        __syncthreads();                 // h16_2 visible

        // ---- Head (warps 0-7) ----
        if (w < 8) {
            float aF[2][4];
#pragma unroll
            for (int m = 0; m < 2; m++)
#pragma unroll
                for (int q = 0; q < 4; q++) aF[m][q] = 0.f;
            gemmH(a_h2, bF, lhi, sxr, aF);
            int d0 = (w & 7) * 8 + 2 * tig;
            float bs0 = sBf[d0], bs1 = sBf[d0 + 1];
#pragma unroll
            for (int m = 0; m < 2; m++) {
                int r0 = g + m * 16, r1 = g + 8 + m * 16;
                float2 v;
                v.x = aF[m][0] + bs0; v.y = aF[m][1] + bs1;
                *reinterpret_cast<float2*>(
                    out + ((size_t)(b0 + r0) * T_ + t) * D_ + d0) = v;
                v.x = aF[m][2] + bs0; v.y = aF[m][3] + bs1;
                *reinterpret_cast<float2*>(
                    out + ((size_t)(b0 + r1) * T_ + t) * D_ + d0) = v;
            }
        }
    }
#undef CONSUME

    // final states from registers
    {
        size_t base = (size_t)B_ * T_ * D_;
        size_t base2 = base + (size_t)B_ * H_;
#pragma unroll
        for (int jt = 0; jt < 2; jt++)
#pragma unroll
            for (int m = 0; m < 2; m++)
#pragma unroll
                for (int hq = 0; hq < 2; hq++) {
                    int row = g + hq * 8 + m * 16;
                    int j0 = w * 16 + jt * 8 + 2 * tig;
                    float2 v1, v2;
                    v1.x = h1r[jt][m][hq][0]; v1.y = h1r[jt][m][hq][1];
                    v2.x = h2r[jt][m][hq][0]; v2.y = h2r[jt][m][hq][1];
                    *reinterpret_cast<float2*>(
                        out + base + (size_t)(b0 + row) * H_ + j0) = v1;
                    *reinterpret_cast<float2*>(
                        out + base2 + (size_t)(b0 + row) * H_ + j0) = v2;
                }
    }
}

// ---------------------------------------------------------------------------
extern "C" void kernel_launch(void* const* d_in, const int* in_sizes, int n_in,
                              void* d_out, int out_size) {
    (void)in_sizes; (void)n_in; (void)out_size;
    const float* x     = (const float*)d_in[0];
    const float* h1    = (const float*)d_in[1];
    const float* h2    = (const float*)d_in[2];
    const float* W_ih1 = (const float*)d_in[3];
    const float* W_hh1 = (const float*)d_in[4];
    const float* b_ih1 = (const float*)d_in[5];
    const float* b_hh1 = (const float*)d_in[6];
    const float* W_ih2 = (const float*)d_in[7];
    const float* W_hh2 = (const float*)d_in[8];
    const float* b_ih2 = (const float*)d_in[9];
    const float* b_hh2 = (const float*)d_in[10];
    const float* W_fc  = (const float*)d_in[11];
    const float* b_fc  = (const float*)d_in[12];
    float* out = (float*)d_out;

    repack_w<<<312, 256>>>(W_ih1, W_hh1, W_ih2, W_hh2);
    repack_head<<<8, 256>>>(W_fc);

    cudaFuncSetAttribute(gru_main, cudaFuncAttributeMaxDynamicSharedMemorySize,
                         SMEM_TOT);

    gru_main<<<NBLK, NTHR, SMEM_TOT>>>(x, h1, h2, b_ih1, b_hh1, b_ih2, b_hh2,
                                       b_fc, out);
}

// round 14
// speedup vs baseline: 1.8345x; 1.8324x over previous
#include <cuda_runtime.h>
#include <cuda_fp16.h>
#include <stdint.h>

#define B_    4096
#define T_    256
#define D_    64
#define H_    256
#define NBLK  128
#define MTILE 32
#define NTHR  512

#define S_H 264   // fp32 h row stride (floats); 264 % 32 == 8 -> conflict-free

// Combined per-warp weight stream, chunk order per step:
//   q 0-1 : Wih1 (K=64)    -> L1 x-part
//   q 2-9 : Whh1           -> L1 h-part
//   q10-17: Whh2           -> L2 h-part (runs BEFORE the h1-publish barrier)
//   q18-25: Wih2           -> L2 x-part
// Layout [w16][q26][t6][lane32], uint4 = lane's n8 x k32 B-frag.
__device__ __align__(16) uint4 g_bW[16 * 26 * 6 * 32];
__device__ __align__(16) uint4 g_bF [8 * 8 * 32 + 512];   // head (8 warps)

__device__ __forceinline__ uint32_t pkh(float a, float b) {
    __half2 h = __floats2half2_rn(a, b);
    return *reinterpret_cast<uint32_t*>(&h);
}
__device__ __forceinline__ void mma16(float* d, const uint32_t* a,
                                      uint32_t b0, uint32_t b1) {
    asm volatile(
        "mma.sync.aligned.m16n8k16.row.col.f32.f16.f16.f32 "
        "{%0,%1,%2,%3}, {%4,%5,%6,%7}, {%8,%9}, {%0,%1,%2,%3};\n"
        : "+f"(d[0]), "+f"(d[1]), "+f"(d[2]), "+f"(d[3])
        : "r"(a[0]), "r"(a[1]), "r"(a[2]), "r"(a[3]), "r"(b0), "r"(b1));
}
__device__ __forceinline__ void ldsm4(uint32_t* r, uint32_t addr) {
    asm volatile("ldmatrix.sync.aligned.m8n8.x4.shared.b16 {%0,%1,%2,%3}, [%4];"
                 : "=r"(r[0]), "=r"(r[1]), "=r"(r[2]), "=r"(r[3]) : "r"(addr));
}
__device__ __forceinline__ float ftanh(float x) {
    float y; asm("tanh.approx.f32 %0, %1;" : "=f"(y) : "f"(x)); return y;
}
__device__ __forceinline__ float fsig(float x) {
    return fmaf(0.5f, ftanh(0.5f * x), 0.5f);
}
__device__ __forceinline__ uint32_t cvta_s(const void* p) {
    return (uint32_t)__cvta_generic_to_shared(p);
}

// ---------------------------------------------------------------------------
// Repack combined blob in the q-order above.
__global__ void repack_w(const float* __restrict__ Wih1,
                         const float* __restrict__ Whh1,
                         const float* __restrict__ Wih2,
                         const float* __restrict__ Whh2) {
    int total = 16 * 26 * 6 * 32;
    for (int o = blockIdx.x * blockDim.x + threadIdx.x; o < total;
         o += gridDim.x * blockDim.x) {
        int lane = o & 31, s = o >> 5;
        int t = s % 6; s /= 6;
        int q = s % 26, w = s / 26;
        int G = t >> 1, jt = t & 1, g = lane >> 2, tig = lane & 3;
        int n = G * H_ + w * 16 + jt * 8 + g;
        const float* W; int K, c2;
        if (q < 2)       { W = Wih1; K = 64;  c2 = q; }
        else if (q < 10) { W = Whh1; K = 256; c2 = q - 2; }
        else if (q < 18) { W = Whh2; K = 256; c2 = q - 10; }
        else             { W = Wih2; K = 256; c2 = q - 18; }
        const float* src = W + (size_t)n * K + c2 * 32 + 2 * tig;
        uint4 v;
        v.x = pkh(src[0],  src[1]);
        v.y = pkh(src[8],  src[9]);
        v.z = pkh(src[16], src[17]);
        v.w = pkh(src[24], src[25]);
        g_bW[o] = v;
    }
}
__global__ void repack_head(const float* __restrict__ W) {
    int total = 8 * 8 * 32;
    for (int o = blockIdx.x * blockDim.x + threadIdx.x; o < total;
         o += gridDim.x * blockDim.x) {
        int lane = o & 31, s = o >> 5;
        int c2 = s & 7, w = s >> 3;
        int g = lane >> 2, tig = lane & 3;
        int n = w * 8 + g;
        const float* src = W + (size_t)n * 256 + c2 * 32 + 2 * tig;
        uint4 v;
        v.x = pkh(src[0],  src[1]);
        v.y = pkh(src[8],  src[9]);
        v.z = pkh(src[16], src[17]);
        v.w = pkh(src[24], src[25]);
        g_bF[o] = v;
    }
}

// ---------------------------------------------------------------------------
// Consume one k32 chunk. Two passes: all half-0 MMAs (12 distinct accs),
// then all half-1 MMAs with ring refill -> same-acc dep distance = 12.
__device__ __forceinline__ void consume_chunk(
    const uint4*& pf, const uint4* pbase, const uint4* pend, uint4 (&buf)[6],
    uint32_t aad0, uint32_t aad1, int c2, int lhi, int sxr,
    float (&aR)[2][2][4], float (&aZ)[2][2][4], float (&aN)[2][2][4]) {
    uint32_t af[2][2][4];
#pragma unroll
    for (int m = 0; m < 2; m++)
#pragma unroll
        for (int ch = 0; ch < 2; ch++) {
            int cc = c2 * 4 + ch * 2 + lhi;
            uint32_t addr = (m ? aad1 : aad0) + (uint32_t)((cc ^ sxr) << 4);
            ldsm4(af[m][ch], addr);
        }
#pragma unroll
    for (int t = 0; t < 6; t++) {
        float (*acc)[2][4] = (t < 2) ? aR : (t < 4) ? aZ : aN;
        int jt = t & 1;
        mma16(acc[jt][0], af[0][0], buf[t].x, buf[t].y);
        mma16(acc[jt][1], af[1][0], buf[t].x, buf[t].y);
    }
#pragma unroll
    for (int t = 0; t < 6; t++) {
        uint4 wv = buf[t];
        buf[t] = *pf; pf += 32;            // persistent ring refill
        if (pf == pend) pf = pbase;        // wrap: same stream every step
        float (*acc)[2][4] = (t < 2) ? aR : (t < 4) ? aZ : aN;
        int jt = t & 1;
        mma16(acc[jt][0], af[0][1], wv.z, wv.w);
        mma16(acc[jt][1], af[1][1], wv.z, wv.w);
    }
}

// Head GEMM (warps 0-7): n8 tile per warp, K=256 (unchanged from R6).
__device__ __forceinline__ void gemmH(uint32_t ah,
                                      const uint4* __restrict__ blobWL,
                                      int lhi, int sxr, float (&acc)[2][4]) {
    uint4 buf[8];
#pragma unroll
    for (int i = 0; i < 8; i++) buf[i] = blobWL[i * 32];
#pragma unroll 1
    for (int c2 = 0; c2 < 8; c2++) {
        uint32_t af[2][2][4];
#pragma unroll
        for (int m = 0; m < 2; m++)
#pragma unroll
            for (int ch = 0; ch < 2; ch++) {
                int cc = c2 * 4 + ch * 2 + lhi;
                uint32_t addr = (m ? ah + 16 * 512 : ah) +
                                (uint32_t)((cc ^ sxr) << 4);
                ldsm4(af[m][ch], addr);
            }
        uint4 wv = buf[c2];
        mma16(acc[0], af[0][0], wv.x, wv.y);
        mma16(acc[1], af[1][0], wv.x, wv.y);
        mma16(acc[0], af[0][1], wv.z, wv.w);
        mma16(acc[1], af[1][1], wv.z, wv.w);
    }
}

__device__ __forceinline__ void zero4(float (&aR)[2][2][4], float (&aZ)[2][2][4],
                                      float (&aNi)[2][2][4],
                                      float (&aNh)[2][2][4]) {
#pragma unroll
    for (int jt = 0; jt < 2; jt++)
#pragma unroll
        for (int m = 0; m < 2; m++)
#pragma unroll
            for (int q = 0; q < 4; q++) {
                aR[jt][m][q] = 0.f; aZ[jt][m][q] = 0.f;
                aNi[jt][m][q] = 0.f; aNh[jt][m][q] = 0.f;
            }
}

// GRU gate math + h update (identical numerics to R6).
__device__ __forceinline__ void epilogue(float (&aR)[2][2][4], float (&aZ)[2][2][4],
                                         float (&aNi)[2][2][4],
                                         float (&aNh)[2][2][4],
                                         const float* __restrict__ hc, float* hn,
                                         char* hn16,
                                         const float* __restrict__ sB,
                                         int w, int g, int tig) {
#pragma unroll
    for (int jt = 0; jt < 2; jt++) {
        int j0 = w * 16 + jt * 8 + 2 * tig;
        float br0 = sB[j0],          br1 = sB[j0 + 1];
        float bz0 = sB[H_ + j0],     bz1 = sB[H_ + j0 + 1];
        float bi0 = sB[2 * H_ + j0], bi1 = sB[2 * H_ + j0 + 1];
        float bh0 = sB[3 * H_ + j0], bh1 = sB[3 * H_ + j0 + 1];
        int cc = 2 * w + jt;
#pragma unroll
        for (int m = 0; m < 2; m++)
#pragma unroll
            for (int hq = 0; hq < 2; hq++) {
                int row = g + hq * 8 + m * 16;
                int q0 = hq * 2, q1 = hq * 2 + 1;
                int i0 = row * S_H + j0;
                float r0 = fsig(aR[jt][m][q0] + br0);
                float r1 = fsig(aR[jt][m][q1] + br1);
                float z0 = fsig(aZ[jt][m][q0] + bz0);
                float z1 = fsig(aZ[jt][m][q1] + bz1);
                float n0 = ftanh(aNi[jt][m][q0] + bi0 + r0 * (aNh[jt][m][q0] + bh0));
                float n1 = ftanh(aNi[jt][m][q1] + bi1 + r1 * (aNh[jt][m][q1] + bh1));
                float h0 = (1.f - z0) * n0 + z0 * hc[i0];
                float h1 = (1.f - z1) * n1 + z1 * hc[i0 + 1];
                float2 v; v.x = h0; v.y = h1;
                *reinterpret_cast<float2*>(hn + i0) = v;
                *reinterpret_cast<__half2*>(
                    hn16 + row * 512 + ((cc ^ (row & 7)) << 4) + tig * 4) =
                    __floats2half2_rn(h0, h1);
            }
    }
}

// ---------------------------------------------------------------------------
extern __shared__ float smem[];

__global__ void __launch_bounds__(NTHR, 1)
gru_main(const float* __restrict__ x, const float* __restrict__ h1g,
         const float* __restrict__ h2g,
         const float* __restrict__ bih1, const float* __restrict__ bhh1,
         const float* __restrict__ bih2, const float* __restrict__ bhh2,
         const float* __restrict__ bfc, float* __restrict__ out) {
    float* sh1 = smem;                      // fp32 h1: 2 buf x 32 x S_H
    float* sh2 = sh1 + 2 * MTILE * S_H;     // fp32 h2
    float* sB1 = sh2 + 2 * MTILE * S_H;     // 4*256
    float* sB2 = sB1 + 4 * H_;              // 4*256
    float* sBf = sB2 + 4 * H_;              // 64
    char*  h16_1 = (char*)(sBf + 64);       // fp16 h1: 2 buf x 32 x 512B
    char*  h16_2 = h16_1 + 2 * 32 * 512;    // fp16 h2
    char*  x16   = h16_2 + 2 * 32 * 512;    // fp16 x : 2 buf x 32 x 128B

    const int tid = threadIdx.x;
    const int w = tid >> 5, lane = tid & 31, g = lane >> 2, tig = lane & 3;
    const int l16 = lane & 15, lhi = lane >> 4, sxr = l16 & 7;
    const int b0 = blockIdx.x * MTILE;

    if (tid < 256) {
        sB1[tid]          = bih1[tid] + bhh1[tid];
        sB1[H_ + tid]     = bih1[H_ + tid] + bhh1[H_ + tid];
        sB1[2 * H_ + tid] = bih1[2 * H_ + tid];
        sB1[3 * H_ + tid] = bhh1[2 * H_ + tid];
        sB2[tid]          = bih2[tid] + bhh2[tid];
        sB2[H_ + tid]     = bih2[H_ + tid] + bhh2[H_ + tid];
        sB2[2 * H_ + tid] = bih2[2 * H_ + tid];
        sB2[3 * H_ + tid] = bhh2[2 * H_ + tid];
        if (tid < D_) sBf[tid] = bfc[tid];

        int cc = tid >> 3, cb = tid & 7;
        for (int i = 0; i < MTILE; i++) {
            float v1 = h1g[(size_t)(b0 + i) * H_ + tid];
            float v2 = h2g[(size_t)(b0 + i) * H_ + tid];
            sh1[i * S_H + tid] = v1;
            sh2[i * S_H + tid] = v2;
            int off = i * 512 + ((cc ^ (i & 7)) << 4) + cb * 2;
            *reinterpret_cast<__half*>(h16_1 + off) = __float2half_rn(v1);
            *reinterpret_cast<__half*>(h16_2 + off) = __float2half_rn(v2);
        }
    }

    const int xr = (tid & 255) >> 3, xcc = tid & 7;
    const float* xbase = x + ((size_t)(b0 + xr) * T_) * D_ + xcc * 8;
    const int xoff = xr * 128 + ((xcc ^ (xr & 7)) << 4);
    if (tid < 256) {
        float4 v0 = *reinterpret_cast<const float4*>(xbase);
        float4 v1 = *reinterpret_cast<const float4*>(xbase + 4);
        uint4 p;
        p.x = pkh(v0.x, v0.y); p.y = pkh(v0.z, v0.w);
        p.z = pkh(v1.x, v1.y); p.w = pkh(v1.z, v1.w);
        *reinterpret_cast<uint4*>(x16 + xoff) = p;
    }

    const uint32_t u16_1 = cvta_s(h16_1) + l16 * 512;
    const uint32_t u16_2 = cvta_s(h16_2) + l16 * 512;
    const uint32_t ux16  = cvta_s(x16) + l16 * 128;
    const uint4* bF = g_bF + (size_t)(w & 7) * 8 * 32 + lane;

    // persistent weight ring: warm once, never restarts (wraps every step)
    const uint4* pbase = g_bW + (size_t)w * 26 * 6 * 32 + lane;
    const uint4* pend  = pbase + 26 * 6 * 32;
    const uint4* pf;
    uint4 buf[6];
#pragma unroll
    for (int i = 0; i < 6; i++) buf[i] = pbase[i * 32];
    pf = pbase + 6 * 32;

    float aR[2][2][4], aZ[2][2][4], aNi[2][2][4], aNh[2][2][4];

    for (int t = 0; t < T_; t++) {
        const int cur = t & 1;
        float* h1c = sh1 + cur * MTILE * S_H;
        float* h1n = sh1 + (cur ^ 1) * MTILE * S_H;
        float* h2c = sh2 + cur * MTILE * S_H;
        float* h2n = sh2 + (cur ^ 1) * MTILE * S_H;
        uint32_t a_h1c = u16_1 + cur * 16384;
        uint32_t a_h1n = u16_1 + (cur ^ 1) * 16384;
        uint32_t a_h2c = u16_2 + cur * 16384;
        uint32_t a_h2n = u16_2 + (cur ^ 1) * 16384;
        uint32_t a_x   = ux16 + cur * 4096;
        char* h1n16 = h16_1 + (cur ^ 1) * 16384;
        char* h2n16 = h16_2 + (cur ^ 1) * 16384;

        __syncthreads();   // x[cur] staged, previous-step writes visible

        float4 vx0, vx1;
        if (tid < 256 && t + 1 < T_) {
            const float* xp = xbase + (size_t)(t + 1) * D_;
            vx0 = *reinterpret_cast<const float4*>(xp);
            vx1 = *reinterpret_cast<const float4*>(xp + 4);
        }

        // ---- Layer 1: q 0-1 (x-part) + q 2-9 (h-part) ----
        zero4(aR, aZ, aNi, aNh);
#pragma unroll 1
        for (int q = 0; q < 2; q++)
            consume_chunk(pf, pbase, pend, buf, a_x, a_x + 2048, q,
                          lhi, sxr, aR, aZ, aNi);
#pragma unroll 1
        for (int q = 0; q < 8; q++)
            consume_chunk(pf, pbase, pend, buf, a_h1c, a_h1c + 8192, q,
                          lhi, sxr, aR, aZ, aNh);
        epilogue(aR, aZ, aNi, aNh, h1c, h1n, h1n16, sB1, w, g, tig);

        // ---- Layer 2 h-part (independent of L1 epilogue): q 10-17 ----
        zero4(aR, aZ, aNi, aNh);
#pragma unroll 1
        for (int q = 0; q < 8; q++)
            consume_chunk(pf, pbase, pend, buf, a_h2c, a_h2c + 8192, q,
                          lhi, sxr, aR, aZ, aNh);
        __syncthreads();   // h1n16 (L1 epilogue) now visible

        // ---- Layer 2 x-part (input = new h1): q 18-25 ----
#pragma unroll 1
        for (int q = 0; q < 8; q++)
            consume_chunk(pf, pbase, pend, buf, a_h1n, a_h1n + 8192, q,
                          lhi, sxr, aR, aZ, aNi);
        epilogue(aR, aZ, aNi, aNh, h2c, h2n, h2n16, sB2, w, g, tig);
        __syncthreads();   // h2n16 visible

        // ---- Head (warps 0-7) ----
        if (w < 8) {
            float aF[2][4];
#pragma unroll
            for (int m = 0; m < 2; m++)
#pragma unroll
                for (int q = 0; q < 4; q++) aF[m][q] = 0.f;
            gemmH(a_h2n, bF, lhi, sxr, aF);
            int d0 = (w & 7) * 8 + 2 * tig;
            float bs0 = sBf[d0], bs1 = sBf[d0 + 1];
#pragma unroll
            for (int m = 0; m < 2; m++) {
                int r0 = g + m * 16, r1 = g + 8 + m * 16;
                float2 v;
                v.x = aF[m][0] + bs0; v.y = aF[m][1] + bs1;
                *reinterpret_cast<float2*>(
                    out + ((size_t)(b0 + r0) * T_ + t) * D_ + d0) = v;
                v.x = aF[m][2] + bs0; v.y = aF[m][3] + bs1;
                *reinterpret_cast<float2*>(
                    out + ((size_t)(b0 + r1) * T_ + t) * D_ + d0) = v;
            }
        }

        // park x_{t+1} into the other fp16 x buffer
        if (tid < 256 && t + 1 < T_) {
            uint4 p;
            p.x = pkh(vx0.x, vx0.y); p.y = pkh(vx0.z, vx0.w);
            p.z = pkh(vx1.x, vx1.y); p.w = pkh(vx1.z, vx1.w);
            *reinterpret_cast<uint4*>(x16 + (cur ^ 1) * 4096 + xoff) = p;
        }
    }
    __syncthreads();

    // final states (t=255 wrote buffer 0)
    if (tid < 256) {
        size_t base = (size_t)B_ * T_ * D_;
        for (int i = 0; i < MTILE; i++) {
            out[base + (size_t)(b0 + i) * H_ + tid] = sh1[i * S_H + tid];
            out[base + (size_t)B_ * H_ + (size_t)(b0 + i) * H_ + tid] =
                sh2[i * S_H + tid];
        }
    }
}

// ---------------------------------------------------------------------------
extern "C" void kernel_launch(void* const* d_in, const int* in_sizes, int n_in,
                              void* d_out, int out_size) {
    (void)in_sizes; (void)n_in; (void)out_size;
    const float* x     = (const float*)d_in[0];
    const float* h1    = (const float*)d_in[1];
    const float* h2    = (const float*)d_in[2];
    const float* W_ih1 = (const float*)d_in[3];
    const float* W_hh1 = (const float*)d_in[4];
    const float* b_ih1 = (const float*)d_in[5];
    const float* b_hh1 = (const float*)d_in[6];
    const float* W_ih2 = (const float*)d_in[7];
    const float* W_hh2 = (const float*)d_in[8];
    const float* b_ih2 = (const float*)d_in[9];
    const float* b_hh2 = (const float*)d_in[10];
    const float* W_fc  = (const float*)d_in[11];
    const float* b_fc  = (const float*)d_in[12];
    float* out = (float*)d_out;

    repack_w<<<312, 256>>>(W_ih1, W_hh1, W_ih2, W_hh2);
    repack_head<<<8, 256>>>(W_fc);

    const int smem_bytes =
        (2 * MTILE * S_H * 2 + 4 * H_ * 2 + 64) * (int)sizeof(float) +
        2 * 32 * 512 * 2 +   // fp16 h1, h2 (double buffered)
        2 * 32 * 128;        // fp16 x (double buffered)
    cudaFuncSetAttribute(gru_main, cudaFuncAttributeMaxDynamicSharedMemorySize,
                         smem_bytes);

    gru_main<<<NBLK, NTHR, smem_bytes>>>(x, h1, h2, b_ih1, b_hh1, b_ih2, b_hh2,
                                         b_fc, out);
}

// round 15
// speedup vs baseline: 2.0996x; 1.1445x over previous
#include <cuda_runtime.h>
#include <cuda_fp16.h>
#include <stdint.h>

#define B_    4096
#define T_    256
#define D_    64
#define H_    256
#define NBLK  128
#define MTILE 32
#define NTHR  512

#define S_H 264   // fp32 h row stride (floats); 264 % 32 == 8 -> conflict-free

// Combined per-layer fp16 weight blobs, 16-warp layout:
//   blob[w16][c2][t=G*2+jt (6)][lane], uint4 = lane's B-frag for n8 x k32.
// Warp w owns gate cols [G*256 + w*16, +16) for each gate G.
__device__ __align__(16) uint4 g_bL1[16 * 10 * 6 * 32 + 512];
__device__ __align__(16) uint4 g_bL2[16 * 16 * 6 * 32 + 512];
__device__ __align__(16) uint4 g_bF [8 * 8 * 32 + 512];   // head: 8 warps

__device__ __forceinline__ uint32_t pkh(float a, float b) {
    __half2 h = __floats2half2_rn(a, b);
    return *reinterpret_cast<uint32_t*>(&h);
}
__device__ __forceinline__ void mma16(float* d, const uint32_t* a,
                                      uint32_t b0, uint32_t b1) {
    asm volatile(
        "mma.sync.aligned.m16n8k16.row.col.f32.f16.f16.f32 "
        "{%0,%1,%2,%3}, {%4,%5,%6,%7}, {%8,%9}, {%0,%1,%2,%3};\n"
        : "+f"(d[0]), "+f"(d[1]), "+f"(d[2]), "+f"(d[3])
        : "r"(a[0]), "r"(a[1]), "r"(a[2]), "r"(a[3]), "r"(b0), "r"(b1));
}
__device__ __forceinline__ void ldsm4(uint32_t* r, uint32_t addr) {
    asm volatile("ldmatrix.sync.aligned.m8n8.x4.shared.b16 {%0,%1,%2,%3}, [%4];"
                 : "=r"(r[0]), "=r"(r[1]), "=r"(r[2]), "=r"(r[3]) : "r"(addr));
}
__device__ __forceinline__ float ftanh(float x) {
    float y; asm("tanh.approx.f32 %0, %1;" : "=f"(y) : "f"(x)); return y;
}
__device__ __forceinline__ float fsig(float x) {
    return fmaf(0.5f, ftanh(0.5f * x), 0.5f);
}
__device__ __forceinline__ uint32_t cvta_s(const void* p) {
    return (uint32_t)__cvta_generic_to_shared(p);
}
// L2-only load (no L1 allocation) for stream-once weight data.
__device__ __forceinline__ uint4 ldcg4(const uint4* p) {
    uint4 v;
    asm volatile("ld.global.cg.v4.u32 {%0,%1,%2,%3}, [%4];"
                 : "=r"(v.x), "=r"(v.y), "=r"(v.z), "=r"(v.w) : "l"(p));
    return v;
}

// ---------------------------------------------------------------------------
// Repack combined layer blob: Wx[3H x Kx] then Wh[3H x 256], 16-warp layout.
__global__ void repack_comb(const float* __restrict__ Wx,
                            const float* __restrict__ Wh, int Kx, int id) {
    uint4* blob = (id == 0) ? g_bL1 : g_bL2;
    int CX = Kx >> 5;
    int NC = CX + 8;
    int total = 16 * NC * 6 * 32;
    for (int o = blockIdx.x * blockDim.x + threadIdx.x; o < total;
         o += gridDim.x * blockDim.x) {
        int lane = o & 31, s = o >> 5;
        int t = s % 6, c2 = (s / 6) % NC, w = s / (6 * NC);
        int G = t >> 1, jt = t & 1, g = lane >> 2, tig = lane & 3;
        int n = G * H_ + w * 16 + jt * 8 + g;
        const float* src = (c2 < CX)
            ? Wx + (size_t)n * Kx + c2 * 32 + 2 * tig
            : Wh + (size_t)n * 256 + (c2 - CX) * 32 + 2 * tig;
        uint4 v;
        v.x = pkh(src[0],  src[1]);
        v.y = pkh(src[8],  src[9]);
        v.z = pkh(src[16], src[17]);
        v.w = pkh(src[24], src[25]);
        blob[o] = v;
    }
}
__global__ void repack_head(const float* __restrict__ W) {
    uint4* blob = g_bF;
    int total = 8 * 8 * 32;
    for (int o = blockIdx.x * blockDim.x + threadIdx.x; o < total;
         o += gridDim.x * blockDim.x) {
        int lane = o & 31, s = o >> 5;
        int c2 = s & 7, w = s >> 3;
        int g = lane >> 2, tig = lane & 3;
        int n = w * 8 + g;
        const float* src = W + (size_t)n * 256 + c2 * 32 + 2 * tig;
        uint4 v;
        v.x = pkh(src[0],  src[1]);
        v.y = pkh(src[8],  src[9]);
        v.z = pkh(src[16], src[17]);
        v.w = pkh(src[24], src[25]);
        blob[o] = v;
    }
}

// ---------------------------------------------------------------------------
// fp16 A tiles in smem: row r (0..31), 16B chunk c stored at chunk (c ^ (r&7)).
// One K-segment; A-frags via ldmatrix, weight ring depth 6 (one chunk).
template <int NC2>
__device__ __forceinline__ void gemm_part(uint32_t aad0, uint32_t aad1,
                                          int lhi, int sxr,
                                          const uint4*& pf, uint4 (&buf)[6],
                                          float (&aR)[2][2][4],
                                          float (&aZ)[2][2][4],
                                          float (&aN)[2][2][4]) {
#pragma unroll 1
    for (int c2 = 0; c2 < NC2; c2++) {
        uint32_t af[2][2][4];
#pragma unroll
        for (int m = 0; m < 2; m++)
#pragma unroll
            for (int ch = 0; ch < 2; ch++) {
                int cc = c2 * 4 + ch * 2 + lhi;
                uint32_t addr = (m ? aad1 : aad0) + (uint32_t)((cc ^ sxr) << 4);
                ldsm4(af[m][ch], addr);
            }
#pragma unroll
        for (int t = 0; t < 6; t++) {
            uint4 wv = buf[t];
            buf[t] = ldcg4(pf);  pf += 32;   // prefetch distance = 6 (L2-only)
            float (*acc)[2][4] = (t < 2) ? aR : (t < 4) ? aZ : aN;
            int jt = t & 1;
            mma16(acc[jt][0], af[0][0], wv.x, wv.y);
            mma16(acc[jt][1], af[1][0], wv.x, wv.y);
            mma16(acc[jt][0], af[0][1], wv.z, wv.w);
            mma16(acc[jt][1], af[1][1], wv.z, wv.w);
        }
    }
}

// Full layer GEMM: x-part (CX chunks) then h-part (8 chunks), one continuous
// weight stream, single warm ring.
template <int CX>
__device__ __forceinline__ void gemmL(uint32_t ax, uint32_t ah, int rbx_shift,
                                      const uint4* __restrict__ blobWL,
                                      int lhi, int sxr,
                                      float (&aR)[2][2][4], float (&aZ)[2][2][4],
                                      float (&aNi)[2][2][4],
                                      float (&aNh)[2][2][4]) {
    const uint4* pf = blobWL;
    uint4 buf[6];
#pragma unroll
    for (int i = 0; i < 6; i++) buf[i] = ldcg4(pf + i * 32);
    pf += 6 * 32;
    gemm_part<CX>(ax, ax + (16u << rbx_shift), lhi, sxr, pf, buf, aR, aZ, aNi);
    gemm_part<8>(ah, ah + 16 * 512, lhi, sxr, pf, buf, aR, aZ, aNh);
}

// Head GEMM (warps 0-7 only): n8 tile per warp, K=256.
__device__ __forceinline__ void gemmH(uint32_t ah,
                                      const uint4* __restrict__ blobWL,
                                      int lhi, int sxr, float (&acc)[2][4]) {
    uint4 buf[8];
#pragma unroll
    for (int i = 0; i < 8; i++) buf[i] = ldcg4(blobWL + i * 32);
#pragma unroll 1
    for (int c2 = 0; c2 < 8; c2++) {
        uint32_t af[2][2][4];
#pragma unroll
        for (int m = 0; m < 2; m++)
#pragma unroll
            for (int ch = 0; ch < 2; ch++) {
                int cc = c2 * 4 + ch * 2 + lhi;
                uint32_t addr = (m ? ah + 16 * 512 : ah) +
                                (uint32_t)((cc ^ sxr) << 4);
                ldsm4(af[m][ch], addr);
            }
        uint4 wv = buf[c2];
        mma16(acc[0], af[0][0], wv.x, wv.y);
        mma16(acc[1], af[1][0], wv.x, wv.y);
        mma16(acc[0], af[0][1], wv.z, wv.w);
        mma16(acc[1], af[1][1], wv.z, wv.w);
    }
}

__device__ __forceinline__ void zero4(float (&aR)[2][2][4], float (&aZ)[2][2][4],
                                      float (&aNi)[2][2][4],
                                      float (&aNh)[2][2][4]) {
#pragma unroll
    for (int jt = 0; jt < 2; jt++)
#pragma unroll
        for (int m = 0; m < 2; m++)
#pragma unroll
            for (int q = 0; q < 4; q++) {
                aR[jt][m][q] = 0.f; aZ[jt][m][q] = 0.f;
                aNi[jt][m][q] = 0.f; aNh[jt][m][q] = 0.f;
            }
}

// GRU gate math + h update. Writes fp32 h' and swizzled fp16 h'.
__device__ __forceinline__ void epilogue(float (&aR)[2][2][4], float (&aZ)[2][2][4],
                                         float (&aNi)[2][2][4],
                                         float (&aNh)[2][2][4],
                                         const float* __restrict__ hc, float* hn,
                                         char* hn16,
                                         const float* __restrict__ sB,
                                         int w, int g, int tig) {
#pragma unroll
    for (int jt = 0; jt < 2; jt++) {
        int j0 = w * 16 + jt * 8 + 2 * tig;
        float br0 = sB[j0],          br1 = sB[j0 + 1];
        float bz0 = sB[H_ + j0],     bz1 = sB[H_ + j0 + 1];
        float bi0 = sB[2 * H_ + j0], bi1 = sB[2 * H_ + j0 + 1];
        float bh0 = sB[3 * H_ + j0], bh1 = sB[3 * H_ + j0 + 1];
        int cc = 2 * w + jt;   // 16B chunk of cols j0..j0+7
#pragma unroll
        for (int m = 0; m < 2; m++)
#pragma unroll
            for (int hq = 0; hq < 2; hq++) {
                int row = g + hq * 8 + m * 16;
                int q0 = hq * 2, q1 = hq * 2 + 1;
                int i0 = row * S_H + j0;
                float r0 = fsig(aR[jt][m][q0] + br0);
                float r1 = fsig(aR[jt][m][q1] + br1);
                float z0 = fsig(aZ[jt][m][q0] + bz0);
                float z1 = fsig(aZ[jt][m][q1] + bz1);
                float n0 = ftanh(aNi[jt][m][q0] + bi0 + r0 * (aNh[jt][m][q0] + bh0));
                float n1 = ftanh(aNi[jt][m][q1] + bi1 + r1 * (aNh[jt][m][q1] + bh1));
                float h0 = (1.f - z0) * n0 + z0 * hc[i0];
                float h1 = (1.f - z1) * n1 + z1 * hc[i0 + 1];
                float2 v; v.x = h0; v.y = h1;
                *reinterpret_cast<float2*>(hn + i0) = v;
                *reinterpret_cast<__half2*>(
                    hn16 + row * 512 + ((cc ^ (row & 7)) << 4) + tig * 4) =
                    __floats2half2_rn(h0, h1);
            }
    }
}

// ---------------------------------------------------------------------------
extern __shared__ float smem[];

__global__ void __launch_bounds__(NTHR, 1)
gru_main(const float* __restrict__ x, const float* __restrict__ h1g,
         const float* __restrict__ h2g,
         const float* __restrict__ bih1, const float* __restrict__ bhh1,
         const float* __restrict__ bih2, const float* __restrict__ bhh2,
         const float* __restrict__ bfc, float* __restrict__ out) {
    float* sh1 = smem;                      // fp32 h1: 2 buf x 32 x S_H
    float* sh2 = sh1 + 2 * MTILE * S_H;     // fp32 h2
    float* sB1 = sh2 + 2 * MTILE * S_H;     // 4*256
    float* sB2 = sB1 + 4 * H_;              // 4*256
    float* sBf = sB2 + 4 * H_;              // 64
    char*  h16_1 = (char*)(sBf + 64);       // fp16 h1: 2 buf x 32 x 512B
    char*  h16_2 = h16_1 + 2 * 32 * 512;    // fp16 h2
    char*  x16   = h16_2 + 2 * 32 * 512;    // fp16 x : 2 buf x 32 x 128B

    const int tid = threadIdx.x;
    const int w = tid >> 5, lane = tid & 31, g = lane >> 2, tig = lane & 3;
    const int l16 = lane & 15, lhi = lane >> 4, sxr = l16 & 7;
    const int b0 = blockIdx.x * MTILE;

    // combined biases into shared (threads 0..255)
    if (tid < 256) {
        sB1[tid]          = bih1[tid] + bhh1[tid];
        sB1[H_ + tid]     = bih1[H_ + tid] + bhh1[H_ + tid];
        sB1[2 * H_ + tid] = bih1[2 * H_ + tid];
        sB1[3 * H_ + tid] = bhh1[2 * H_ + tid];
        sB2[tid]          = bih2[tid] + bhh2[tid];
        sB2[H_ + tid]     = bih2[H_ + tid] + bhh2[H_ + tid];
        sB2[2 * H_ + tid] = bih2[2 * H_ + tid];
        sB2[3 * H_ + tid] = bhh2[2 * H_ + tid];
        if (tid < D_) sBf[tid] = bfc[tid];

        // init h buffer 0 (fp32 + swizzled fp16)
        int cc = tid >> 3, cb = tid & 7;
        for (int i = 0; i < MTILE; i++) {
            float v1 = h1g[(size_t)(b0 + i) * H_ + tid];
            float v2 = h2g[(size_t)(b0 + i) * H_ + tid];
            sh1[i * S_H + tid] = v1;
            sh2[i * S_H + tid] = v2;
            int off = i * 512 + ((cc ^ (i & 7)) << 4) + cb * 2;
            *reinterpret_cast<__half*>(h16_1 + off) = __float2half_rn(v1);
            *reinterpret_cast<__half*>(h16_2 + off) = __float2half_rn(v2);
        }
    }

    // x staging coords (threads 0..255)
    const int xr = (tid & 255) >> 3, xcc = tid & 7;
    const float* xbase = x + ((size_t)(b0 + xr) * T_) * D_ + xcc * 8;
    const int xoff = xr * 128 + ((xcc ^ (xr & 7)) << 4);

    if (tid < 256) {
        float4 v0 = *reinterpret_cast<const float4*>(xbase);
        float4 v1 = *reinterpret_cast<const float4*>(xbase + 4);
        uint4 p;
        p.x = pkh(v0.x, v0.y); p.y = pkh(v0.z, v0.w);
        p.z = pkh(v1.x, v1.y); p.w = pkh(v1.z, v1.w);
        *reinterpret_cast<uint4*>(x16 + xoff) = p;
    }

    // shared-space byte addresses for ldmatrix (lane row folded in)
    const uint32_t u16_1 = cvta_s(h16_1) + l16 * 512;
    const uint32_t u16_2 = cvta_s(h16_2) + l16 * 512;
    const uint32_t ux16  = cvta_s(x16) + l16 * 128;

    // per-warp blob bases (lane folded in)
    const uint4* bL1 = g_bL1 + (size_t)w * 10 * 6 * 32 + lane;
    const uint4* bL2 = g_bL2 + (size_t)w * 16 * 6 * 32 + lane;
    const uint4* bF  = g_bF  + (size_t)(w & 7) * 8 * 32 + lane;

    float aR[2][2][4], aZ[2][2][4], aNi[2][2][4], aNh[2][2][4];

    for (int t = 0; t < T_; t++) {
        const int cur = t & 1;
        float* h1c = sh1 + cur * MTILE * S_H;
        float* h1n = sh1 + (cur ^ 1) * MTILE * S_H;
        float* h2c = sh2 + cur * MTILE * S_H;
        float* h2n = sh2 + (cur ^ 1) * MTILE * S_H;
        uint32_t a_h1c = u16_1 + cur * 16384;
        uint32_t a_h1n = u16_1 + (cur ^ 1) * 16384;
        uint32_t a_h2c = u16_2 + cur * 16384;
        uint32_t a_h2n = u16_2 + (cur ^ 1) * 16384;
        uint32_t a_x   = ux16 + cur * 4096;
        char* h1n16 = h16_1 + (cur ^ 1) * 16384;
        char* h2n16 = h16_2 + (cur ^ 1) * 16384;

        __syncthreads();   // x[cur] staged, previous-step writes visible

        // issue x_{t+1} loads early
        float4 vx0, vx1;
        if (tid < 256 && t + 1 < T_) {
            const float* xp = xbase + (size_t)(t + 1) * D_;
            vx0 = *reinterpret_cast<const float4*>(xp);
            vx1 = *reinterpret_cast<const float4*>(xp + 4);
        }

        // ---- Layer 1 (fused K=64+256 weight stream) ----
        zero4(aR, aZ, aNi, aNh);
        gemmL<2>(a_x, a_h1c, 7, bL1, lhi, sxr, aR, aZ, aNi, aNh);
        epilogue(aR, aZ, aNi, aNh, h1c, h1n, h1n16, sB1, w, g, tig);
        __syncthreads();

        // ---- Layer 2 (input = new h1; fused K=256+256) ----
        zero4(aR, aZ, aNi, aNh);
        gemmL<8>(a_h1n, a_h2c, 9, bL2, lhi, sxr, aR, aZ, aNi, aNh);
        epilogue(aR, aZ, aNi, aNh, h2c, h2n, h2n16, sB2, w, g, tig);
        __syncthreads();

        // ---- Head (warps 0-7): y_t = h2_new @ W_fc^T + b_fc ----
        if (w < 8) {
            float aF[2][4];
#pragma unroll
            for (int m = 0; m < 2; m++)
#pragma unroll
                for (int q = 0; q < 4; q++) aF[m][q] = 0.f;
            gemmH(a_h2n, bF, lhi, sxr, aF);
            int d0 = w * 8 + 2 * tig;
            float bs0 = sBf[d0], bs1 = sBf[d0 + 1];
#pragma unroll
            for (int m = 0; m < 2; m++) {
                int r0 = g + m * 16, r1 = g + 8 + m * 16;
                float2 v;
                v.x = aF[m][0] + bs0; v.y = aF[m][1] + bs1;
                *reinterpret_cast<float2*>(
                    out + ((size_t)(b0 + r0) * T_ + t) * D_ + d0) = v;
                v.x = aF[m][2] + bs0; v.y = aF[m][3] + bs1;
                *reinterpret_cast<float2*>(
                    out + ((size_t)(b0 + r1) * T_ + t) * D_ + d0) = v;
            }
        }

        // park x_{t+1} into the other fp16 x buffer
        if (tid < 256 && t + 1 < T_) {
            uint4 p;
            p.x = pkh(vx0.x, vx0.y); p.y = pkh(vx0.z, vx0.w);
            p.z = pkh(vx1.x, vx1.y); p.w = pkh(vx1.z, vx1.w);
            *reinterpret_cast<uint4*>(x16 + (cur ^ 1) * 4096 + xoff) = p;
        }
    }
    __syncthreads();

    // final states (t=255 wrote buffer 0)
    if (tid < 256) {
        size_t base = (size_t)B_ * T_ * D_;
        for (int i = 0; i < MTILE; i++) {
            out[base + (size_t)(b0 + i) * H_ + tid] = sh1[i * S_H + tid];
            out[base + (size_t)B_ * H_ + (size_t)(b0 + i) * H_ + tid] =
                sh2[i * S_H + tid];
        }
    }
}

// ---------------------------------------------------------------------------
extern "C" void kernel_launch(void* const* d_in, const int* in_sizes, int n_in,
                              void* d_out, int out_size) {
    (void)in_sizes; (void)n_in; (void)out_size;
    const float* x     = (const float*)d_in[0];
    const float* h1    = (const float*)d_in[1];
    const float* h2    = (const float*)d_in[2];
    const float* W_ih1 = (const float*)d_in[3];
    const float* W_hh1 = (const float*)d_in[4];
    const float* b_ih1 = (const float*)d_in[5];
    const float* b_hh1 = (const float*)d_in[6];
    const float* W_ih2 = (const float*)d_in[7];
    const float* W_hh2 = (const float*)d_in[8];
    const float* b_ih2 = (const float*)d_in[9];
    const float* b_hh2 = (const float*)d_in[10];
    const float* W_fc  = (const float*)d_in[11];
    const float* b_fc  = (const float*)d_in[12];
    float* out = (float*)d_out;

    repack_comb<<<120, 256>>>(W_ih1, W_hh1, 64, 0);
    repack_comb<<<192, 256>>>(W_ih2, W_hh2, 256, 1);
    repack_head<<<8, 256>>>(W_fc);

    const int smem_bytes =
        (2 * MTILE * S_H * 2 + 4 * H_ * 2 + 64) * (int)sizeof(float) +
        2 * 32 * 512 * 2 +   // fp16 h1, h2 (double buffered)
        2 * 32 * 128;        // fp16 x (double buffered)
    cudaFuncSetAttribute(gru_main, cudaFuncAttributeMaxDynamicSharedMemorySize,
                         smem_bytes);

    gru_main<<<NBLK, NTHR, smem_bytes>>>(x, h1, h2, b_ih1, b_hh1, b_ih2, b_hh2,
                                         b_fc, out);
}